// round 6
// baseline (speedup 1.0000x reference)
#include <cuda_runtime.h>
#include <cuda_bf16.h>
#include <cstdint>

// ---------------- problem constants ----------------
constexpr int B = 2;
constexpr int D = 64;
constexpr int N = 96 * 96;      // 9216
constexpr int ITERS = 4;
constexpr float STEP = 0.5f;
constexpr float KBW = 0.3f;

constexpr int BM = 128;
constexpr int BN = 128;
constexpr int THREADS = 512;
constexpr int NT = N / BN;      // 72

// Tile image: 2 chunks x [64 d][64 pt] bf16, 128B swizzled rows = 16384 B
constexpr int IMG = 16384;

__device__ __align__(16) unsigned char g_xh[(size_t)B * NT * IMG];
__device__ __align__(16) unsigned char g_xl[(size_t)B * NT * IMG];

// ---------------- smem layout (bytes) ----------------
constexpr int XM_H = 0;              // 16 KB
constexpr int XM_L = 16384;
constexpr int XN_BASE = 32768;       // 3 stages x 32 KB (H +0, L +16384)
constexpr int XN_STRIDE = 32768;
constexpr int SDEN = 131072;         // 256 f32
constexpr int MBAR = 132096;         // full[3], empty[3], mbx
constexpr int SMEM_BYTES = 132224;
// epilogue reuse: sO0 f32[64][132] at 0, sO1 at 33792

// ---------------- asm helpers ----------------
__device__ __forceinline__ uint32_t smem_u32(const void* p) {
    uint32_t a;
    asm("{ .reg .u64 t; cvta.to.shared.u64 t, %1; cvt.u32.u64 %0, t; }"
        : "=r"(a) : "l"(p));
    return a;
}

__device__ __forceinline__ uint32_t swz(uint32_t o) {
    return o ^ ((o >> 3) & 0x70);
}

#define MBAR_INIT(mbar, cnt) \
    asm volatile("mbarrier.init.shared.b64 [%0], %1;" :: "r"(mbar), "r"(cnt) : "memory")

#define MBAR_EXPECT_TX(mbar, bytes) \
    asm volatile("mbarrier.arrive.expect_tx.shared.b64 _, [%0], %1;" \
                 :: "r"(mbar), "r"(bytes) : "memory")

#define MBAR_ARRIVE(mbar) \
    asm volatile("mbarrier.arrive.shared.b64 _, [%0];" :: "r"(mbar) : "memory")

#define MBAR_WAIT(mbar, parity) do {                                          \
    uint32_t _m = (mbar), _p = (parity);                                      \
    asm volatile(                                                             \
        "{\n\t.reg .pred P1;\n\t"                                             \
        "WAIT_LOOP_%=:\n\t"                                                   \
        "mbarrier.try_wait.parity.acquire.cta.shared::cta.b64 P1, [%0], %1, 0x989680;\n\t" \
        "@P1 bra.uni WAIT_DONE_%=;\n\t"                                       \
        "bra.uni WAIT_LOOP_%=;\n\t"                                           \
        "WAIT_DONE_%=:\n\t}"                                                  \
        :: "r"(_m), "r"(_p) : "memory");                                      \
} while (0)

__device__ __forceinline__ void bulk_g2s(uint32_t dst, const void* src,
                                         uint32_t bytes, uint32_t mbar) {
    asm volatile(
        "cp.async.bulk.shared::cluster.global.mbarrier::complete_tx::bytes "
        "[%0], [%1], %2, [%3];"
        :: "r"(dst), "l"(__cvta_generic_to_global(src)), "r"(bytes), "r"(mbar)
        : "memory");
}

#define LDSM_X4(r, addr)                                                     \
    asm volatile("ldmatrix.sync.aligned.m8n8.x4.shared.b16 {%0,%1,%2,%3}, [%4];" \
        : "=r"((r)[0]), "=r"((r)[1]), "=r"((r)[2]), "=r"((r)[3]) : "r"(addr))

#define LDSM_X4_T(r, addr)                                                   \
    asm volatile("ldmatrix.sync.aligned.m8n8.x4.trans.shared.b16 {%0,%1,%2,%3}, [%4];" \
        : "=r"((r)[0]), "=r"((r)[1]), "=r"((r)[2]), "=r"((r)[3]) : "r"(addr))

__device__ __forceinline__ void hmma(float* c, const uint32_t* a, const uint32_t* b) {
    asm volatile(
        "mma.sync.aligned.m16n8k16.row.col.f32.bf16.bf16.f32 "
        "{%0,%1,%2,%3}, {%4,%5,%6,%7}, {%8,%9}, {%0,%1,%2,%3};"
        : "+f"(c[0]), "+f"(c[1]), "+f"(c[2]), "+f"(c[3])
        : "r"(a[0]), "r"(a[1]), "r"(a[2]), "r"(a[3]), "r"(b[0]), "r"(b[1]));
}

__device__ __forceinline__ uint32_t pack_bf2(float hi, float lo) {
    uint32_t r;
    asm("cvt.rn.bf16x2.f32 %0, %1, %2;" : "=r"(r) : "f"(hi), "f"(lo));
    return r;
}

__device__ __forceinline__ uint32_t pack2(__nv_bfloat16 a, __nv_bfloat16 b) {
    return (uint32_t)__bfloat16_as_ushort(a) |
           ((uint32_t)__bfloat16_as_ushort(b) << 16);
}

__device__ __forceinline__ void split_pair(float v0, float v1,
                                           uint32_t& hw, uint32_t& lw) {
    __nv_bfloat16 h0 = __float2bfloat16_rn(v0);
    __nv_bfloat16 h1 = __float2bfloat16_rn(v1);
    __nv_bfloat16 l0 = __float2bfloat16_rn(v0 - __bfloat162float(h0));
    __nv_bfloat16 l1 = __float2bfloat16_rn(v1 - __bfloat162float(h1));
    hw = pack2(h0, h1);
    lw = pack2(l0, l1);
}

// replicate a float into both lanes of an f32x2 register (CSE-able)
__device__ __forceinline__ uint64_t pk2(float x) {
    uint64_t r;
    asm("mov.b64 %0, {%1,%1};" : "=l"(r) : "f"(x));
    return r;
}

// packed exp(KBW*s) for two values via fma.rn.f32x2
__device__ __forceinline__ void expk_pair(float s0, float s1, float& e0, float& e1) {
    const float C = KBW * 1.4426950408889634f;
    uint64_t sp, t, r, mr, f, p;
    asm("mov.b64 %0, {%1,%2};" : "=l"(sp) : "f"(s0), "f"(s1));
    asm("mul.rn.f32x2 %0, %1, %2;" : "=l"(t) : "l"(sp), "l"(pk2(C)));
    asm("add.rn.f32x2 %0, %1, %2;" : "=l"(r) : "l"(t), "l"(pk2(12582912.0f)));
    asm("fma.rn.f32x2 %0, %1, %2, %3;"
        : "=l"(mr) : "l"(r), "l"(pk2(-1.0f)), "l"(pk2(12582912.0f)));
    asm("add.rn.f32x2 %0, %1, %2;" : "=l"(f) : "l"(mr), "l"(t));
    p = pk2(1.3333558146428443e-3f);
    asm("fma.rn.f32x2 %0, %1, %2, %3;"
        : "=l"(p) : "l"(p), "l"(f), "l"(pk2(9.618129107628477e-3f)));
    asm("fma.rn.f32x2 %0, %1, %2, %3;"
        : "=l"(p) : "l"(p), "l"(f), "l"(pk2(5.550410866482158e-2f)));
    asm("fma.rn.f32x2 %0, %1, %2, %3;"
        : "=l"(p) : "l"(p), "l"(f), "l"(pk2(2.402265069591007e-1f)));
    asm("fma.rn.f32x2 %0, %1, %2, %3;"
        : "=l"(p) : "l"(p), "l"(f), "l"(pk2(6.931471805599453e-1f)));
    asm("fma.rn.f32x2 %0, %1, %2, %3;"
        : "=l"(p) : "l"(p), "l"(f), "l"(pk2(1.0f)));
    uint32_t r0b, r1b, p0b, p1b;
    asm("mov.b64 {%0,%1}, %2;" : "=r"(r0b), "=r"(r1b) : "l"(r));
    asm("mov.b64 {%0,%1}, %2;" : "=r"(p0b), "=r"(p1b) : "l"(p));
    // (ii<<23) == (bits(r)<<23): low 23 bits of 0x4B400000 are zero
    e0 = __int_as_float(p0b + (r0b << 23));
    e1 = __int_as_float(p1b + (r1b << 23));
}

// Copy x_in (B, D, N) into output slice i=0 of (B, ITERS+1, D, N)
__global__ void copy_x0_kernel(const float* __restrict__ x, float* __restrict__ out) {
    int i = blockIdx.x * blockDim.x + threadIdx.x;
    int total = B * D * N / 4;
    if (i < total) {
        int perb = D * N / 4;
        int b = i / perb;
        int r = i - b * perb;
        float4 v = ((const float4*)x)[i];
        ((float4*)out)[(size_t)b * ((ITERS + 1) * D * N / 4) + r] = v;
    }
}

// Convert x slice `it` into hi/lo bf16 swizzled tile images.
__global__ __launch_bounds__(256)
void convert_kernel(const float* __restrict__ out, int it) {
    const int t = blockIdx.x, b = blockIdx.y;
    const int tid = threadIdx.x;
    const float* xs = out + ((size_t)b * (ITERS + 1) + it) * (size_t)(D * N);
    unsigned char* ph = g_xh + (size_t)(b * NT + t) * IMG;
    unsigned char* pl = g_xl + (size_t)(b * NT + t) * IMG;
    #pragma unroll
    for (int q = 0; q < 4; ++q) {
        int task = q * 256 + tid;          // c(2) x d(64) x g(8)
        int c = task >> 9, rem = task & 511;
        int d = rem >> 3, g = rem & 7;
        int n0 = t * BN + c * 64 + g * 8;
        const float4* s = (const float4*)(xs + (size_t)d * N + n0);
        float4 v0 = s[0], v1 = s[1];
        uint32_t hp[4], lp[4];
        split_pair(v0.x, v0.y, hp[0], lp[0]);
        split_pair(v0.z, v0.w, hp[1], lp[1]);
        split_pair(v1.x, v1.y, hp[2], lp[2]);
        split_pair(v1.z, v1.w, hp[3], lp[3]);
        uint32_t off = c * 8192 + swz((uint32_t)(d * 128 + g * 16));
        *(uint4*)(ph + off) = make_uint4(hp[0], hp[1], hp[2], hp[3]);
        *(uint4*)(pl + off) = make_uint4(lp[0], lp[1], lp[2], lp[3]);
    }
}

// ---------------- main kernel ----------------
__global__ __launch_bounds__(THREADS, 1)
void ms_mma_kernel(float* __restrict__ out, int it) {
    extern __shared__ unsigned char smc[];
    uint32_t sb = smem_u32(smc);

    const int tid = threadIdx.x;
    const int l = tid & 31;
    const int w = tid >> 5;
    const int wm = w >> 1;       // 8 m-groups of 16 rows
    const int wn = w & 1;        // 2 n-groups of 64 cols

    const int b = blockIdx.y;
    const int m0 = blockIdx.x * BM;
    const float* __restrict__ xin = out + ((size_t)b * (ITERS + 1) + it) * (size_t)(D * N);
    float* __restrict__ xout = (float*)xin + (size_t)D * N;

    const int l7 = l & 7, l8 = l & 8, l16h = (l & 16) >> 1, lq = l >> 2, lr = l & 3;

    const uint32_t mbF = sb + MBAR;            // full[3] at +0,+8,+16
    const uint32_t mbE = sb + MBAR + 24;       // empty[3]
    const uint32_t mbx = sb + MBAR + 48;

    // ---- prologue ----
    if (tid == 0) {
        MBAR_INIT(mbF, 1);  MBAR_INIT(mbF + 8, 1);  MBAR_INIT(mbF + 16, 1);
        MBAR_INIT(mbE, 16); MBAR_INIT(mbE + 8, 16); MBAR_INIT(mbE + 16, 16);
        MBAR_INIT(mbx, 1);
    }
    __syncthreads();
    const unsigned char* gh = g_xh + (size_t)b * NT * IMG;
    const unsigned char* gl = g_xl + (size_t)b * NT * IMG;
    if (tid == 0) {
        MBAR_EXPECT_TX(mbx, 2 * IMG);
        bulk_g2s(sb + XM_H, gh + (size_t)blockIdx.x * IMG, IMG, mbx);
        bulk_g2s(sb + XM_L, gl + (size_t)blockIdx.x * IMG, IMG, mbx);
        #pragma unroll
        for (int u = 0; u < 2; ++u) {
            MBAR_EXPECT_TX(mbF + u * 8, 2 * IMG);
            bulk_g2s(sb + XN_BASE + u * XN_STRIDE, gh + (size_t)u * IMG, IMG, mbF + u * 8);
            bulk_g2s(sb + XN_BASE + u * XN_STRIDE + IMG, gl + (size_t)u * IMG, IMG, mbF + u * 8);
        }
    }

    // per-warp address components
    const int mchunk = (wm >> 2) * 8192;
    const int mcol = (wm & 3) * 16 + l8;
    const int nchunk = wn * 8192;

    // ---- hoist XM A-fragments (loop-invariant) ----
    MBAR_WAIT(mbx, 0);
    uint32_t Ah[4][4], Al[4][4];
    #pragma unroll
    for (int k = 0; k < 4; ++k) {
        const uint32_t offA =
            swz((uint32_t)((k * 16 + l7 + l16h) * 128 + mcol * 2)) + mchunk;
        LDSM_X4_T(Ah[k], sb + XM_H + offA);
        LDSM_X4_T(Al[k], sb + XM_L + offA);
    }

    float accO[8][4];
    #pragma unroll
    for (int j = 0; j < 8; ++j)
        #pragma unroll
        for (int c = 0; c < 4; ++c) accO[j][c] = 0.0f;
    float dsum0 = 0.0f, dsum1 = 0.0f;

    for (int t = 0; t < NT; ++t) {
        // producer: prefetch tile t+2 into stage (t+2)%3
        if (tid == 0) {
            const int u = t + 2;
            if (u < NT) {
                const int us = u % 3, uj = u / 3;
                if (u >= 3) MBAR_WAIT(mbE + us * 8, (uj - 1) & 1);
                MBAR_EXPECT_TX(mbF + us * 8, 2 * IMG);
                const uint32_t nb = sb + XN_BASE + us * XN_STRIDE;
                bulk_g2s(nb, gh + (size_t)u * IMG, IMG, mbF + us * 8);
                bulk_g2s(nb + IMG, gl + (size_t)u * IMG, IMG, mbF + us * 8);
            }
        }
        const int cs = t % 3;
        const uint32_t XNB = sb + XN_BASE + cs * XN_STRIDE;
        MBAR_WAIT(mbF + cs * 8, (t / 3) & 1);

        // ---- MMA1: S[16m x 64n] per warp, k = 64 d, 3 split passes ----
        float accS[8][4];
        #pragma unroll
        for (int j = 0; j < 8; ++j)
            #pragma unroll
            for (int c = 0; c < 4; ++c) accS[j][c] = 0.0f;

        #pragma unroll
        for (int k = 0; k < 4; ++k) {
            const int drowB = k * 16 + l7 + l8;
            #pragma unroll
            for (int np = 0; np < 4; ++np) {
                uint32_t Bh[4], Bl[4];
                const uint32_t offB =
                    swz((uint32_t)(drowB * 128 + (np * 16 + l16h) * 2)) + nchunk;
                LDSM_X4_T(Bh, XNB + offB);
                LDSM_X4_T(Bl, XNB + IMG + offB);
                hmma(accS[2 * np],     Ah[k], Bh);
                hmma(accS[2 * np + 1], Ah[k], Bh + 2);
                hmma(accS[2 * np],     Ah[k], Bl);
                hmma(accS[2 * np + 1], Ah[k], Bl + 2);
                hmma(accS[2 * np],     Al[k], Bh);
                hmma(accS[2 * np + 1], Al[k], Bh + 2);
            }
        }

        // ---- K = exp(KBW*S) in-register -> MMA2 A fragments (hi/lo) ----
        uint32_t AKh[4][4], AKl[4][4];
        #pragma unroll
        for (int nj = 0; nj < 8; ++nj) {
            float e0, e1, e2, e3;
            expk_pair(accS[nj][0], accS[nj][1], e0, e1);
            expk_pair(accS[nj][2], accS[nj][3], e2, e3);
            dsum0 += e0 + e1;
            dsum1 += e2 + e3;
            uint32_t h01 = pack_bf2(e1, e0);
            uint32_t h23 = pack_bf2(e3, e2);
            float f0 = e0 - __int_as_float(h01 << 16);
            float f1 = e1 - __int_as_float(h01 & 0xFFFF0000u);
            float f2 = e2 - __int_as_float(h23 << 16);
            float f3 = e3 - __int_as_float(h23 & 0xFFFF0000u);
            uint32_t l01 = pack_bf2(f1, f0);
            uint32_t l23 = pack_bf2(f3, f2);
            const int ks = nj >> 1, r0 = (nj & 1) * 2;
            AKh[ks][r0] = h01;  AKh[ks][r0 + 1] = h23;
            AKl[ks][r0] = l01;  AKl[ks][r0 + 1] = l23;
        }

        // ---- MMA2: O[16m x 64d] per warp += K(regs) . Xn, k = 64 n-slice ----
        #pragma unroll
        for (int ks = 0; ks < 4; ++ks) {
            const int kcol = ks * 16 + l8;
            #pragma unroll
            for (int dg = 0; dg < 4; ++dg) {
                const int dd = dg * 16 + l7 + l16h;
                const uint32_t off =
                    swz((uint32_t)(dd * 128 + kcol * 2)) + nchunk;
                uint32_t Bh[4], Bl[4];
                LDSM_X4(Bh, XNB + off);
                LDSM_X4(Bl, XNB + IMG + off);
                hmma(accO[2 * dg],     AKh[ks], Bh);
                hmma(accO[2 * dg + 1], AKh[ks], Bh + 2);
                hmma(accO[2 * dg],     AKh[ks], Bl);
                hmma(accO[2 * dg + 1], AKh[ks], Bl + 2);
                hmma(accO[2 * dg],     AKl[ks], Bh);
                hmma(accO[2 * dg + 1], AKl[ks], Bh + 2);
            }
        }

        // done reading stage cs
        if (l == 0) MBAR_ARRIVE(mbE + cs * 8);
    }

    // ---- den reduction ----
    float* sDen = (float*)(smc + SDEN);     // [2][128]
    {
        float v0 = dsum0, v1 = dsum1;
        v0 += __shfl_xor_sync(0xFFFFFFFFu, v0, 1);
        v0 += __shfl_xor_sync(0xFFFFFFFFu, v0, 2);
        v1 += __shfl_xor_sync(0xFFFFFFFFu, v1, 1);
        v1 += __shfl_xor_sync(0xFFFFFFFFu, v1, 2);
        if (lr == 0) {
            sDen[wn * 128 + wm * 16 + lq] = v0;
            sDen[wn * 128 + wm * 16 + 8 + lq] = v1;
        }
    }
    __syncthreads();   // all warps done with all tiles; sDen visible

    // ---- partial-O epilogue: scale by STEP/den, write per n-group region ----
    const int mA = wm * 16 + lq, mB = mA + 8;
    const float scA = STEP / (sDen[mA] + sDen[128 + mA]);
    const float scB = STEP / (sDen[mB] + sDen[128 + mB]);
    float* sO = (float*)(smc + wn * 33792);   // [64 d][132 m]
    #pragma unroll
    for (int dg = 0; dg < 4; ++dg)
        #pragma unroll
        for (int s = 0; s < 2; ++s) {
            const float* c = accO[2 * dg + s];
            const int dbase = dg * 16 + s * 8 + 2 * lr;
            sO[dbase * 132 + mA]       = c[0] * scA;
            sO[(dbase + 1) * 132 + mA] = c[1] * scA;
            sO[dbase * 132 + mB]       = c[2] * scB;
            sO[(dbase + 1) * 132 + mB] = c[3] * scB;
        }
    __syncthreads();

    // ---- combine partials + blend with x, store ----
    const float* sO0 = (const float*)(smc);
    const float* sO1 = (const float*)(smc + 33792);
    #pragma unroll
    for (int q = 0; q < 4; ++q) {
        int task = q * THREADS + tid;       // dd(64) x mq(32)
        int dd = task >> 5, mq = task & 31;
        float4 o0 = *(const float4*)&sO0[dd * 132 + mq * 4];
        float4 o1 = *(const float4*)&sO1[dd * 132 + mq * 4];
        float4 x = *(const float4*)(xin + (size_t)dd * N + m0 + mq * 4);
        float4 r;
        r.x = fmaf(1.0f - STEP, x.x, o0.x + o1.x);
        r.y = fmaf(1.0f - STEP, x.y, o0.y + o1.y);
        r.z = fmaf(1.0f - STEP, x.z, o0.z + o1.z);
        r.w = fmaf(1.0f - STEP, x.w, o0.w + o1.w);
        *(float4*)(xout + (size_t)dd * N + m0 + mq * 4) = r;
    }
}

extern "C" void kernel_launch(void* const* d_in, const int* in_sizes, int n_in,
                              void* d_out, int out_size) {
    const float* x = (const float*)d_in[0];
    float* out = (float*)d_out;

    cudaFuncSetAttribute(ms_mma_kernel,
                         cudaFuncAttributeMaxDynamicSharedMemorySize, SMEM_BYTES);

    int copy_total = B * D * N / 4;
    copy_x0_kernel<<<(copy_total + 255) / 256, 256>>>(x, out);

    dim3 grid(NT, B);
    for (int it = 0; it < ITERS; ++it) {
        convert_kernel<<<grid, 256>>>(out, it);
        ms_mma_kernel<<<grid, THREADS, SMEM_BYTES>>>(out, it);
    }
}

// round 7
// speedup vs baseline: 1.2129x; 1.2129x over previous
#include <cuda_runtime.h>
#include <cuda_fp16.h>
#include <cstdint>

// ---------------- problem constants ----------------
constexpr int B = 2;
constexpr int D = 64;
constexpr int N = 96 * 96;      // 9216
constexpr int ITERS = 4;
constexpr float STEP = 0.5f;
constexpr float KBW = 0.3f;
constexpr float LOG2E = 1.4426950408889634f;

constexpr int BM = 128;
constexpr int BN = 128;
constexpr int THREADS = 512;
constexpr int NT = N / BN;      // 72

// Tile image: 2 chunks x [64 d][64 pt] fp16, 128B swizzled rows = 16384 B
constexpr int IMG = 16384;

__device__ __align__(16) unsigned char g_xh[(size_t)B * NT * IMG];
__device__ __align__(16) unsigned char g_xl[(size_t)B * NT * IMG];
__device__ float g_tsh[(size_t)B * N];   // per-point log2 shift

// ---------------- smem layout (bytes) ----------------
constexpr int XM_H = 0;              // 16 KB
constexpr int XM_L = 16384;
constexpr int XN_BASE = 32768;       // 3 stages x 32 KB (H +0, L +16384)
constexpr int XN_STRIDE = 32768;
constexpr int SDEN = 131072;         // 256 f32
constexpr int MBAR = 132096;         // full[3], empty[3], mbx
constexpr int SMEM_BYTES = 132224;
// epilogue reuse: sO0 f32[64][132] at 0, sO1 at 33792

// ---------------- asm helpers ----------------
__device__ __forceinline__ uint32_t smem_u32(const void* p) {
    uint32_t a;
    asm("{ .reg .u64 t; cvta.to.shared.u64 t, %1; cvt.u32.u64 %0, t; }"
        : "=r"(a) : "l"(p));
    return a;
}

__device__ __forceinline__ uint32_t swz(uint32_t o) {
    return o ^ ((o >> 3) & 0x70);
}

#define MBAR_INIT(mbar, cnt) \
    asm volatile("mbarrier.init.shared.b64 [%0], %1;" :: "r"(mbar), "r"(cnt) : "memory")

#define MBAR_EXPECT_TX(mbar, bytes) \
    asm volatile("mbarrier.arrive.expect_tx.shared.b64 _, [%0], %1;" \
                 :: "r"(mbar), "r"(bytes) : "memory")

#define MBAR_ARRIVE(mbar) \
    asm volatile("mbarrier.arrive.shared.b64 _, [%0];" :: "r"(mbar) : "memory")

#define MBAR_WAIT(mbar, parity) do {                                          \
    uint32_t _m = (mbar), _p = (parity);                                      \
    asm volatile(                                                             \
        "{\n\t.reg .pred P1;\n\t"                                             \
        "WAIT_LOOP_%=:\n\t"                                                   \
        "mbarrier.try_wait.parity.acquire.cta.shared::cta.b64 P1, [%0], %1, 0x989680;\n\t" \
        "@P1 bra.uni WAIT_DONE_%=;\n\t"                                       \
        "bra.uni WAIT_LOOP_%=;\n\t"                                           \
        "WAIT_DONE_%=:\n\t}"                                                  \
        :: "r"(_m), "r"(_p) : "memory");                                      \
} while (0)

__device__ __forceinline__ void bulk_g2s(uint32_t dst, const void* src,
                                         uint32_t bytes, uint32_t mbar) {
    asm volatile(
        "cp.async.bulk.shared::cluster.global.mbarrier::complete_tx::bytes "
        "[%0], [%1], %2, [%3];"
        :: "r"(dst), "l"(__cvta_generic_to_global(src)), "r"(bytes), "r"(mbar)
        : "memory");
}

#define LDSM_X4(r, addr)                                                     \
    asm volatile("ldmatrix.sync.aligned.m8n8.x4.shared.b16 {%0,%1,%2,%3}, [%4];" \
        : "=r"((r)[0]), "=r"((r)[1]), "=r"((r)[2]), "=r"((r)[3]) : "r"(addr))

#define LDSM_X4_T(r, addr)                                                   \
    asm volatile("ldmatrix.sync.aligned.m8n8.x4.trans.shared.b16 {%0,%1,%2,%3}, [%4];" \
        : "=r"((r)[0]), "=r"((r)[1]), "=r"((r)[2]), "=r"((r)[3]) : "r"(addr))

__device__ __forceinline__ void hmma(float* c, const uint32_t* a, const uint32_t* b) {
    asm volatile(
        "mma.sync.aligned.m16n8k16.row.col.f32.f16.f16.f32 "
        "{%0,%1,%2,%3}, {%4,%5,%6,%7}, {%8,%9}, {%0,%1,%2,%3};"
        : "+f"(c[0]), "+f"(c[1]), "+f"(c[2]), "+f"(c[3])
        : "r"(a[0]), "r"(a[1]), "r"(a[2]), "r"(a[3]), "r"(b[0]), "r"(b[1]));
}

// pack two f32 into f16x2 (lo = second arg), saturating to finite
__device__ __forceinline__ uint32_t pack_f16(float hi, float lo) {
    uint32_t r;
    asm("cvt.rn.satfinite.f16x2.f32 %0, %1, %2;" : "=r"(r) : "f"(hi), "f"(lo));
    return r;
}

__device__ __forceinline__ uint32_t pack2h(__half a, __half b) {
    return (uint32_t)__half_as_ushort(a) |
           ((uint32_t)__half_as_ushort(b) << 16);
}

__device__ __forceinline__ void split_pair(float v0, float v1,
                                           uint32_t& hw, uint32_t& lw) {
    __half h0 = __float2half_rn(v0);
    __half h1 = __float2half_rn(v1);
    __half l0 = __float2half_rn(v0 - __half2float(h0));
    __half l1 = __float2half_rn(v1 - __half2float(h1));
    hw = pack2h(h0, h1);
    lw = pack2h(l0, l1);
}

// replicate a float into both lanes of an f32x2 register
__device__ __forceinline__ uint64_t pk2(float x) {
    uint64_t r;
    asm("mov.b64 %0, {%1,%1};" : "=l"(r) : "f"(x));
    return r;
}

// packed 2^(s*C + nts) for two values via fma.rn.f32x2 (nts = -shift, packed)
__device__ __forceinline__ void expk_pair(float s0, float s1, uint64_t nts,
                                          float& e0, float& e1) {
    const float C = KBW * LOG2E;
    uint64_t sp, t, r, mr, f, p;
    asm("mov.b64 %0, {%1,%2};" : "=l"(sp) : "f"(s0), "f"(s1));
    asm("fma.rn.f32x2 %0, %1, %2, %3;" : "=l"(t) : "l"(sp), "l"(pk2(C)), "l"(nts));
    asm("add.rn.f32x2 %0, %1, %2;" : "=l"(r) : "l"(t), "l"(pk2(12582912.0f)));
    asm("fma.rn.f32x2 %0, %1, %2, %3;"
        : "=l"(mr) : "l"(r), "l"(pk2(-1.0f)), "l"(pk2(12582912.0f)));
    asm("add.rn.f32x2 %0, %1, %2;" : "=l"(f) : "l"(mr), "l"(t));
    p = pk2(1.3333558146428443e-3f);
    asm("fma.rn.f32x2 %0, %1, %2, %3;"
        : "=l"(p) : "l"(p), "l"(f), "l"(pk2(9.618129107628477e-3f)));
    asm("fma.rn.f32x2 %0, %1, %2, %3;"
        : "=l"(p) : "l"(p), "l"(f), "l"(pk2(5.550410866482158e-2f)));
    asm("fma.rn.f32x2 %0, %1, %2, %3;"
        : "=l"(p) : "l"(p), "l"(f), "l"(pk2(2.402265069591007e-1f)));
    asm("fma.rn.f32x2 %0, %1, %2, %3;"
        : "=l"(p) : "l"(p), "l"(f), "l"(pk2(6.931471805599453e-1f)));
    asm("fma.rn.f32x2 %0, %1, %2, %3;"
        : "=l"(p) : "l"(p), "l"(f), "l"(pk2(1.0f)));
    uint32_t r0b, r1b, p0b, p1b;
    asm("mov.b64 {%0,%1}, %2;" : "=r"(r0b), "=r"(r1b) : "l"(r));
    asm("mov.b64 {%0,%1}, %2;" : "=r"(p0b), "=r"(p1b) : "l"(p));
    e0 = __int_as_float(p0b + (r0b << 23));
    e1 = __int_as_float(p1b + (r1b << 23));
}

// Copy x_in (B, D, N) into output slice i=0 of (B, ITERS+1, D, N)
__global__ void copy_x0_kernel(const float* __restrict__ x, float* __restrict__ out) {
    int i = blockIdx.x * blockDim.x + threadIdx.x;
    int total = B * D * N / 4;
    if (i < total) {
        int perb = D * N / 4;
        int b = i / perb;
        int r = i - b * perb;
        float4 v = ((const float4*)x)[i];
        ((float4*)out)[(size_t)b * ((ITERS + 1) * D * N / 4) + r] = v;
    }
}

// Convert x slice `it` into hi/lo fp16 swizzled tile images + per-point shift.
__global__ __launch_bounds__(256)
void convert_kernel(const float* __restrict__ out, int it) {
    const int t = blockIdx.x, b = blockIdx.y;
    const int tid = threadIdx.x;
    const float* xs = out + ((size_t)b * (ITERS + 1) + it) * (size_t)(D * N);
    unsigned char* ph = g_xh + (size_t)(b * NT + t) * IMG;
    unsigned char* pl = g_xl + (size_t)(b * NT + t) * IMG;
    #pragma unroll
    for (int q = 0; q < 4; ++q) {
        int task = q * 256 + tid;          // c(2) x d(64) x g(8)
        int c = task >> 9, rem = task & 511;
        int d = rem >> 3, g = rem & 7;
        int n0 = t * BN + c * 64 + g * 8;
        const float4* s = (const float4*)(xs + (size_t)d * N + n0);
        float4 v0 = s[0], v1 = s[1];
        uint32_t hp[4], lp[4];
        split_pair(v0.x, v0.y, hp[0], lp[0]);
        split_pair(v0.z, v0.w, hp[1], lp[1]);
        split_pair(v1.x, v1.y, hp[2], lp[2]);
        split_pair(v1.z, v1.w, hp[3], lp[3]);
        uint32_t off = c * 8192 + swz((uint32_t)(d * 128 + g * 16));
        *(uint4*)(ph + off) = make_uint4(hp[0], hp[1], hp[2], hp[3]);
        *(uint4*)(pl + off) = make_uint4(lp[0], lp[1], lp[2], lp[3]);
    }
    // per-point squared norm -> log2 shift (coalesced across n)
    if (tid < BN) {
        int n = t * BN + tid;
        float s = 0.0f;
        #pragma unroll 8
        for (int d = 0; d < D; ++d) {
            float v = xs[(size_t)d * N + n];
            s = fmaf(v, v, s);
        }
        g_tsh[(size_t)b * N + n] = fmaf(KBW * LOG2E, s, 2.0f);
    }
}

// ---------------- main kernel ----------------
__global__ __launch_bounds__(THREADS, 1)
void ms_mma_kernel(float* __restrict__ out, int it) {
    extern __shared__ unsigned char smc[];
    uint32_t sb = smem_u32(smc);

    const int tid = threadIdx.x;
    const int l = tid & 31;
    const int w = tid >> 5;
    const int wm = w >> 1;       // 8 m-groups of 16 rows
    const int wn = w & 1;        // 2 n-groups of 64 cols

    const int b = blockIdx.y;
    const int m0 = blockIdx.x * BM;
    const float* __restrict__ xin = out + ((size_t)b * (ITERS + 1) + it) * (size_t)(D * N);
    float* __restrict__ xout = (float*)xin + (size_t)D * N;

    const int l7 = l & 7, l8 = l & 8, l16h = (l & 16) >> 1, lq = l >> 2, lr = l & 3;

    const uint32_t mbF = sb + MBAR;            // full[3] at +0,+8,+16
    const uint32_t mbE = sb + MBAR + 24;       // empty[3]
    const uint32_t mbx = sb + MBAR + 48;

    // ---- prologue ----
    if (tid == 0) {
        MBAR_INIT(mbF, 1);  MBAR_INIT(mbF + 8, 1);  MBAR_INIT(mbF + 16, 1);
        MBAR_INIT(mbE, 16); MBAR_INIT(mbE + 8, 16); MBAR_INIT(mbE + 16, 16);
        MBAR_INIT(mbx, 1);
    }
    __syncthreads();
    const unsigned char* gh = g_xh + (size_t)b * NT * IMG;
    const unsigned char* gl = g_xl + (size_t)b * NT * IMG;
    if (tid == 0) {
        MBAR_EXPECT_TX(mbx, 2 * IMG);
        bulk_g2s(sb + XM_H, gh + (size_t)blockIdx.x * IMG, IMG, mbx);
        bulk_g2s(sb + XM_L, gl + (size_t)blockIdx.x * IMG, IMG, mbx);
        #pragma unroll
        for (int u = 0; u < 2; ++u) {
            MBAR_EXPECT_TX(mbF + u * 8, 2 * IMG);
            bulk_g2s(sb + XN_BASE + u * XN_STRIDE, gh + (size_t)u * IMG, IMG, mbF + u * 8);
            bulk_g2s(sb + XN_BASE + u * XN_STRIDE + IMG, gl + (size_t)u * IMG, IMG, mbF + u * 8);
        }
    }

    // per-warp address components
    const int mchunk = (wm >> 2) * 8192;
    const int mcol = (wm & 3) * 16 + l8;
    const int nchunk = wn * 8192;

    // per-thread K-column shifts (rows mA, mA+8)
    const int mA = wm * 16 + lq;
    const uint64_t ntsA = pk2(-g_tsh[(size_t)b * N + m0 + mA]);
    const uint64_t ntsB = pk2(-g_tsh[(size_t)b * N + m0 + mA + 8]);

    const uint32_t oneh = 0x3C003C00u;   // fp16 {1,1}
    const uint32_t bOne[2] = {oneh, oneh};

    float accO[8][4];
    #pragma unroll
    for (int j = 0; j < 8; ++j)
        #pragma unroll
        for (int c = 0; c < 4; ++c) accO[j][c] = 0.0f;
    float accD[4] = {0.0f, 0.0f, 0.0f, 0.0f};

    MBAR_WAIT(mbx, 0);

    for (int t = 0; t < NT; ++t) {
        // producer: prefetch tile t+2 into stage (t+2)%3
        if (tid == 0) {
            const int u = t + 2;
            if (u < NT) {
                const int us = u % 3, uj = u / 3;
                if (u >= 3) MBAR_WAIT(mbE + us * 8, (uj - 1) & 1);
                MBAR_EXPECT_TX(mbF + us * 8, 2 * IMG);
                const uint32_t nb = sb + XN_BASE + us * XN_STRIDE;
                bulk_g2s(nb, gh + (size_t)u * IMG, IMG, mbF + us * 8);
                bulk_g2s(nb + IMG, gl + (size_t)u * IMG, IMG, mbF + us * 8);
            }
        }
        const int cs = t % 3;
        const uint32_t XNB = sb + XN_BASE + cs * XN_STRIDE;
        MBAR_WAIT(mbF + cs * 8, (t / 3) & 1);

        // ---- MMA1: S[16m x 64n] per warp, k = 64 d, 3 split passes ----
        float accS[8][4];
        #pragma unroll
        for (int j = 0; j < 8; ++j)
            #pragma unroll
            for (int c = 0; c < 4; ++c) accS[j][c] = 0.0f;

        #pragma unroll
        for (int k = 0; k < 4; ++k) {
            uint32_t Ah[4], Al[4];
            const uint32_t offA =
                swz((uint32_t)((k * 16 + l7 + l16h) * 128 + mcol * 2)) + mchunk;
            LDSM_X4_T(Ah, sb + XM_H + offA);
            LDSM_X4_T(Al, sb + XM_L + offA);
            const int drowB = k * 16 + l7 + l8;
            #pragma unroll
            for (int np = 0; np < 4; ++np) {
                uint32_t Bh[4], Bl[4];
                const uint32_t offB =
                    swz((uint32_t)(drowB * 128 + (np * 16 + l16h) * 2)) + nchunk;
                LDSM_X4_T(Bh, XNB + offB);
                LDSM_X4_T(Bl, XNB + IMG + offB);
                hmma(accS[2 * np],     Ah, Bh);
                hmma(accS[2 * np + 1], Ah, Bh + 2);
                hmma(accS[2 * np],     Ah, Bl);
                hmma(accS[2 * np + 1], Ah, Bl + 2);
                hmma(accS[2 * np],     Al, Bh);
                hmma(accS[2 * np + 1], Al, Bh + 2);
            }
        }

        // ---- K' = 2^(C*S - tsh_m) in-register -> fp16 MMA2 A fragments ----
        uint32_t AKh[4][4];
        #pragma unroll
        for (int nj = 0; nj < 8; ++nj) {
            float e0, e1, e2, e3;
            expk_pair(accS[nj][0], accS[nj][1], ntsA, e0, e1);
            expk_pair(accS[nj][2], accS[nj][3], ntsB, e2, e3);
            const int ks = nj >> 1, r0 = (nj & 1) * 2;
            AKh[ks][r0]     = pack_f16(e1, e0);
            AKh[ks][r0 + 1] = pack_f16(e3, e2);
        }

        // ---- MMA2: O[16m x 64d] per warp += Kh . (Xh + Xl), k = 64 n-slice;
        //      den via all-ones column ----
        #pragma unroll
        for (int ks = 0; ks < 4; ++ks) {
            hmma(accD, AKh[ks], bOne);
            const int kcol = ks * 16 + l8;
            #pragma unroll
            for (int dg = 0; dg < 4; ++dg) {
                const int dd = dg * 16 + l7 + l16h;
                const uint32_t off =
                    swz((uint32_t)(dd * 128 + kcol * 2)) + nchunk;
                uint32_t Bh[4], Bl[4];
                LDSM_X4(Bh, XNB + off);
                LDSM_X4(Bl, XNB + IMG + off);
                hmma(accO[2 * dg],     AKh[ks], Bh);
                hmma(accO[2 * dg + 1], AKh[ks], Bh + 2);
                hmma(accO[2 * dg],     AKh[ks], Bl);
                hmma(accO[2 * dg + 1], AKh[ks], Bl + 2);
            }
        }

        // done reading stage cs
        if (l == 0) MBAR_ARRIVE(mbE + cs * 8);
    }

    // ---- den: accD[0]=rows lq, accD[2]=rows lq+8 (all quad lanes equal) ----
    float* sDen = (float*)(smc + SDEN);     // [2][128]
    if (lr == 0) {
        sDen[wn * 128 + mA] = accD[0];
        sDen[wn * 128 + mA + 8] = accD[2];
    }
    __syncthreads();   // all warps done with all tiles; sDen visible

    // ---- partial-O epilogue: scale by STEP/den, write per n-group region ----
    const int mB2 = mA + 8;
    const float scA = STEP / (sDen[mA] + sDen[128 + mA]);
    const float scB = STEP / (sDen[mB2] + sDen[128 + mB2]);
    float* sO = (float*)(smc + wn * 33792);   // [64 d][132 m]
    #pragma unroll
    for (int dg = 0; dg < 4; ++dg)
        #pragma unroll
        for (int s = 0; s < 2; ++s) {
            const float* c = accO[2 * dg + s];
            const int dbase = dg * 16 + s * 8 + 2 * lr;
            sO[dbase * 132 + mA]        = c[0] * scA;
            sO[(dbase + 1) * 132 + mA]  = c[1] * scA;
            sO[dbase * 132 + mB2]       = c[2] * scB;
            sO[(dbase + 1) * 132 + mB2] = c[3] * scB;
        }
    __syncthreads();

    // ---- combine partials + blend with x, store ----
    const float* sO0 = (const float*)(smc);
    const float* sO1 = (const float*)(smc + 33792);
    #pragma unroll
    for (int q = 0; q < 4; ++q) {
        int task = q * THREADS + tid;       // dd(64) x mq(32)
        int dd = task >> 5, mq = task & 31;
        float4 o0 = *(const float4*)&sO0[dd * 132 + mq * 4];
        float4 o1 = *(const float4*)&sO1[dd * 132 + mq * 4];
        float4 x = *(const float4*)(xin + (size_t)dd * N + m0 + mq * 4);
        float4 r;
        r.x = fmaf(1.0f - STEP, x.x, o0.x + o1.x);
        r.y = fmaf(1.0f - STEP, x.y, o0.y + o1.y);
        r.z = fmaf(1.0f - STEP, x.z, o0.z + o1.z);
        r.w = fmaf(1.0f - STEP, x.w, o0.w + o1.w);
        *(float4*)(xout + (size_t)dd * N + m0 + mq * 4) = r;
    }
}

extern "C" void kernel_launch(void* const* d_in, const int* in_sizes, int n_in,
                              void* d_out, int out_size) {
    const float* x = (const float*)d_in[0];
    float* out = (float*)d_out;

    cudaFuncSetAttribute(ms_mma_kernel,
                         cudaFuncAttributeMaxDynamicSharedMemorySize, SMEM_BYTES);

    int copy_total = B * D * N / 4;
    copy_x0_kernel<<<(copy_total + 255) / 256, 256>>>(x, out);

    dim3 grid(NT, B);
    for (int it = 0; it < ITERS; ++it) {
        convert_kernel<<<grid, 256>>>(out, it);
        ms_mma_kernel<<<grid, THREADS, SMEM_BYTES>>>(out, it);
    }
}

// round 8
// speedup vs baseline: 1.4037x; 1.1573x over previous
#include <cuda_runtime.h>
#include <cuda_fp16.h>
#include <cstdint>

// ---------------- problem constants ----------------
constexpr int B = 2;
constexpr int D = 64;
constexpr int N = 96 * 96;      // 9216
constexpr int ITERS = 4;
constexpr float STEP = 0.5f;
constexpr float KBW = 0.3f;
constexpr float LOG2E = 1.4426950408889634f;

constexpr int BM = 128;
constexpr int BN = 128;
constexpr int THREADS = 512;
constexpr int NT = N / BN;      // 72

// Tile image: 2 chunks x [64 d][64 pt] fp16, 128B swizzled rows = 16384 B
constexpr int IMG = 16384;

__device__ __align__(16) unsigned char g_xh[(size_t)B * NT * IMG];
__device__ __align__(16) unsigned char g_xl[(size_t)B * NT * IMG];
__device__ float g_tsh[(size_t)B * N];   // per-point log2 shift

// ---------------- smem layout (bytes) ----------------
constexpr int XM_H = 0;              // 16 KB
constexpr int XM_L = 16384;
constexpr int XN_BASE = 32768;       // 3 stages x 32 KB (H +0, L +16384)
constexpr int XN_STRIDE = 32768;
constexpr int SDEN = 131072;         // 256 f32
constexpr int MBAR = 132096;         // full[3], empty[3], mbx
constexpr int SMEM_BYTES = 132224;
// epilogue reuse: sO0 f32[64][132] at 0, sO1 at 33792

// ---------------- asm helpers ----------------
__device__ __forceinline__ uint32_t smem_u32(const void* p) {
    uint32_t a;
    asm("{ .reg .u64 t; cvta.to.shared.u64 t, %1; cvt.u32.u64 %0, t; }"
        : "=r"(a) : "l"(p));
    return a;
}

__device__ __forceinline__ uint32_t swz(uint32_t o) {
    return o ^ ((o >> 3) & 0x70);
}

#define MBAR_INIT(mbar, cnt) \
    asm volatile("mbarrier.init.shared.b64 [%0], %1;" :: "r"(mbar), "r"(cnt) : "memory")

#define MBAR_EXPECT_TX(mbar, bytes) \
    asm volatile("mbarrier.arrive.expect_tx.shared.b64 _, [%0], %1;" \
                 :: "r"(mbar), "r"(bytes) : "memory")

#define MBAR_ARRIVE(mbar) \
    asm volatile("mbarrier.arrive.shared.b64 _, [%0];" :: "r"(mbar) : "memory")

#define MBAR_WAIT(mbar, parity) do {                                          \
    uint32_t _m = (mbar), _p = (parity);                                      \
    asm volatile(                                                             \
        "{\n\t.reg .pred P1;\n\t"                                             \
        "WAIT_LOOP_%=:\n\t"                                                   \
        "mbarrier.try_wait.parity.acquire.cta.shared::cta.b64 P1, [%0], %1, 0x989680;\n\t" \
        "@P1 bra.uni WAIT_DONE_%=;\n\t"                                       \
        "bra.uni WAIT_LOOP_%=;\n\t"                                           \
        "WAIT_DONE_%=:\n\t}"                                                  \
        :: "r"(_m), "r"(_p) : "memory");                                      \
} while (0)

__device__ __forceinline__ void bulk_g2s(uint32_t dst, const void* src,
                                         uint32_t bytes, uint32_t mbar) {
    asm volatile(
        "cp.async.bulk.shared::cluster.global.mbarrier::complete_tx::bytes "
        "[%0], [%1], %2, [%3];"
        :: "r"(dst), "l"(__cvta_generic_to_global(src)), "r"(bytes), "r"(mbar)
        : "memory");
}

#define LDSM_X4(r, addr)                                                     \
    asm volatile("ldmatrix.sync.aligned.m8n8.x4.shared.b16 {%0,%1,%2,%3}, [%4];" \
        : "=r"((r)[0]), "=r"((r)[1]), "=r"((r)[2]), "=r"((r)[3]) : "r"(addr))

#define LDSM_X4_T(r, addr)                                                   \
    asm volatile("ldmatrix.sync.aligned.m8n8.x4.trans.shared.b16 {%0,%1,%2,%3}, [%4];" \
        : "=r"((r)[0]), "=r"((r)[1]), "=r"((r)[2]), "=r"((r)[3]) : "r"(addr))

__device__ __forceinline__ void hmma(float* c, const uint32_t* a, const uint32_t* b) {
    asm volatile(
        "mma.sync.aligned.m16n8k16.row.col.f32.f16.f16.f32 "
        "{%0,%1,%2,%3}, {%4,%5,%6,%7}, {%8,%9}, {%0,%1,%2,%3};"
        : "+f"(c[0]), "+f"(c[1]), "+f"(c[2]), "+f"(c[3])
        : "r"(a[0]), "r"(a[1]), "r"(a[2]), "r"(a[3]), "r"(b[0]), "r"(b[1]));
}

// pack two f32 into f16x2 (lo = second arg), saturating to finite
__device__ __forceinline__ uint32_t pack_f16(float hi, float lo) {
    uint32_t r;
    asm("cvt.rn.satfinite.f16x2.f32 %0, %1, %2;" : "=r"(r) : "f"(hi), "f"(lo));
    return r;
}

__device__ __forceinline__ uint32_t pack2h(__half a, __half b) {
    return (uint32_t)__half_as_ushort(a) |
           ((uint32_t)__half_as_ushort(b) << 16);
}

__device__ __forceinline__ void split_pair(float v0, float v1,
                                           uint32_t& hw, uint32_t& lw) {
    __half h0 = __float2half_rn(v0);
    __half h1 = __float2half_rn(v1);
    __half l0 = __float2half_rn(v0 - __half2float(h0));
    __half l1 = __float2half_rn(v1 - __half2float(h1));
    hw = pack2h(h0, h1);
    lw = pack2h(l0, l1);
}

// replicate a float into both lanes of an f32x2 register
__device__ __forceinline__ uint64_t pk2(float x) {
    uint64_t r;
    asm("mov.b64 %0, {%1,%1};" : "=l"(r) : "f"(x));
    return r;
}

// packed 2^(s*C + nts) for two values via fma.rn.f32x2 (nts = -shift, packed)
__device__ __forceinline__ void expk_pair(float s0, float s1, uint64_t nts,
                                          float& e0, float& e1) {
    const float C = KBW * LOG2E;
    uint64_t sp, t, r, mr, f, p;
    asm("mov.b64 %0, {%1,%2};" : "=l"(sp) : "f"(s0), "f"(s1));
    asm("fma.rn.f32x2 %0, %1, %2, %3;" : "=l"(t) : "l"(sp), "l"(pk2(C)), "l"(nts));
    asm("add.rn.f32x2 %0, %1, %2;" : "=l"(r) : "l"(t), "l"(pk2(12582912.0f)));
    asm("fma.rn.f32x2 %0, %1, %2, %3;"
        : "=l"(mr) : "l"(r), "l"(pk2(-1.0f)), "l"(pk2(12582912.0f)));
    asm("add.rn.f32x2 %0, %1, %2;" : "=l"(f) : "l"(mr), "l"(t));
    p = pk2(1.3333558146428443e-3f);
    asm("fma.rn.f32x2 %0, %1, %2, %3;"
        : "=l"(p) : "l"(p), "l"(f), "l"(pk2(9.618129107628477e-3f)));
    asm("fma.rn.f32x2 %0, %1, %2, %3;"
        : "=l"(p) : "l"(p), "l"(f), "l"(pk2(5.550410866482158e-2f)));
    asm("fma.rn.f32x2 %0, %1, %2, %3;"
        : "=l"(p) : "l"(p), "l"(f), "l"(pk2(2.402265069591007e-1f)));
    asm("fma.rn.f32x2 %0, %1, %2, %3;"
        : "=l"(p) : "l"(p), "l"(f), "l"(pk2(6.931471805599453e-1f)));
    asm("fma.rn.f32x2 %0, %1, %2, %3;"
        : "=l"(p) : "l"(p), "l"(f), "l"(pk2(1.0f)));
    uint32_t r0b, r1b, p0b, p1b;
    asm("mov.b64 {%0,%1}, %2;" : "=r"(r0b), "=r"(r1b) : "l"(r));
    asm("mov.b64 {%0,%1}, %2;" : "=r"(p0b), "=r"(p1b) : "l"(p));
    e0 = __int_as_float(p0b + (r0b << 23));
    e1 = __int_as_float(p1b + (r1b << 23));
}

// Copy x_in (B, D, N) into output slice i=0 of (B, ITERS+1, D, N)
__global__ void copy_x0_kernel(const float* __restrict__ x, float* __restrict__ out) {
    int i = blockIdx.x * blockDim.x + threadIdx.x;
    int total = B * D * N / 4;
    if (i < total) {
        int perb = D * N / 4;
        int b = i / perb;
        int r = i - b * perb;
        float4 v = ((const float4*)x)[i];
        ((float4*)out)[(size_t)b * ((ITERS + 1) * D * N / 4) + r] = v;
    }
}

// Convert x slice `it` into hi/lo fp16 swizzled tile images + per-point shift.
__global__ __launch_bounds__(256)
void convert_kernel(const float* __restrict__ out, int it) {
    const int t = blockIdx.x, b = blockIdx.y;
    const int tid = threadIdx.x;
    const float* xs = out + ((size_t)b * (ITERS + 1) + it) * (size_t)(D * N);
    unsigned char* ph = g_xh + (size_t)(b * NT + t) * IMG;
    unsigned char* pl = g_xl + (size_t)(b * NT + t) * IMG;
    #pragma unroll
    for (int q = 0; q < 4; ++q) {
        int task = q * 256 + tid;          // c(2) x d(64) x g(8)
        int c = task >> 9, rem = task & 511;
        int d = rem >> 3, g = rem & 7;
        int n0 = t * BN + c * 64 + g * 8;
        const float4* s = (const float4*)(xs + (size_t)d * N + n0);
        float4 v0 = s[0], v1 = s[1];
        uint32_t hp[4], lp[4];
        split_pair(v0.x, v0.y, hp[0], lp[0]);
        split_pair(v0.z, v0.w, hp[1], lp[1]);
        split_pair(v1.x, v1.y, hp[2], lp[2]);
        split_pair(v1.z, v1.w, hp[3], lp[3]);
        uint32_t off = c * 8192 + swz((uint32_t)(d * 128 + g * 16));
        *(uint4*)(ph + off) = make_uint4(hp[0], hp[1], hp[2], hp[3]);
        *(uint4*)(pl + off) = make_uint4(lp[0], lp[1], lp[2], lp[3]);
    }
    // per-point squared norm -> log2 shift (coalesced across n)
    if (tid < BN) {
        int n = t * BN + tid;
        float s = 0.0f;
        #pragma unroll 8
        for (int d = 0; d < D; ++d) {
            float v = xs[(size_t)d * N + n];
            s = fmaf(v, v, s);
        }
        g_tsh[(size_t)b * N + n] = fmaf(KBW * LOG2E, s, 2.0f);
    }
}

// ---------------- main kernel ----------------
__global__ __launch_bounds__(THREADS, 1)
void ms_mma_kernel(float* __restrict__ out, int it) {
    extern __shared__ unsigned char smc[];
    uint32_t sb = smem_u32(smc);

    const int tid = threadIdx.x;
    const int l = tid & 31;
    const int w = tid >> 5;
    const int wm = w >> 1;       // 8 m-groups of 16 rows
    const int wn = w & 1;        // 2 n-groups of 64 cols

    const int b = blockIdx.y;
    const int m0 = blockIdx.x * BM;
    const float* __restrict__ xin = out + ((size_t)b * (ITERS + 1) + it) * (size_t)(D * N);
    float* __restrict__ xout = (float*)xin + (size_t)D * N;

    const int l7 = l & 7, l8 = l & 8, l16h = (l & 16) >> 1, lq = l >> 2, lr = l & 3;

    const uint32_t mbF = sb + MBAR;            // full[3] at +0,+8,+16
    const uint32_t mbE = sb + MBAR + 24;       // empty[3]
    const uint32_t mbx = sb + MBAR + 48;

    // ---- prologue ----
    if (tid == 0) {
        MBAR_INIT(mbF, 1);  MBAR_INIT(mbF + 8, 1);  MBAR_INIT(mbF + 16, 1);
        MBAR_INIT(mbE, 16); MBAR_INIT(mbE + 8, 16); MBAR_INIT(mbE + 16, 16);
        MBAR_INIT(mbx, 1);
    }
    __syncthreads();
    const unsigned char* gh = g_xh + (size_t)b * NT * IMG;
    const unsigned char* gl = g_xl + (size_t)b * NT * IMG;
    if (tid == 0) {
        MBAR_EXPECT_TX(mbx, 2 * IMG);
        bulk_g2s(sb + XM_H, gh + (size_t)blockIdx.x * IMG, IMG, mbx);
        bulk_g2s(sb + XM_L, gl + (size_t)blockIdx.x * IMG, IMG, mbx);
        #pragma unroll
        for (int u = 0; u < 2; ++u) {
            MBAR_EXPECT_TX(mbF + u * 8, 2 * IMG);
            bulk_g2s(sb + XN_BASE + u * XN_STRIDE, gh + (size_t)u * IMG, IMG, mbF + u * 8);
            bulk_g2s(sb + XN_BASE + u * XN_STRIDE + IMG, gl + (size_t)u * IMG, IMG, mbF + u * 8);
        }
    }

    // per-warp address components
    const int mchunk = (wm >> 2) * 8192;
    const int mcol = (wm & 3) * 16 + l8;
    const int nchunk = wn * 8192;

    // per-thread K-column shifts (rows mA, mA+8)
    const int mA = wm * 16 + lq;
    const uint64_t ntsA = pk2(-g_tsh[(size_t)b * N + m0 + mA]);
    const uint64_t ntsB = pk2(-g_tsh[(size_t)b * N + m0 + mA + 8]);

    const uint32_t oneh = 0x3C003C00u;   // fp16 {1,1}
    const uint32_t bOne[2] = {oneh, oneh};

    float accO[8][4];
    #pragma unroll
    for (int j = 0; j < 8; ++j)
        #pragma unroll
        for (int c = 0; c < 4; ++c) accO[j][c] = 0.0f;
    float accD[4] = {0.0f, 0.0f, 0.0f, 0.0f};

    MBAR_WAIT(mbx, 0);

    for (int t = 0; t < NT; ++t) {
        // producer: prefetch tile t+2 into stage (t+2)%3
        if (tid == 0) {
            const int u = t + 2;
            if (u < NT) {
                const int us = u % 3, uj = u / 3;
                if (u >= 3) MBAR_WAIT(mbE + us * 8, (uj - 1) & 1);
                MBAR_EXPECT_TX(mbF + us * 8, 2 * IMG);
                const uint32_t nb = sb + XN_BASE + us * XN_STRIDE;
                bulk_g2s(nb, gh + (size_t)u * IMG, IMG, mbF + us * 8);
                bulk_g2s(nb + IMG, gl + (size_t)u * IMG, IMG, mbF + us * 8);
            }
        }
        const int cs = t % 3;
        const uint32_t XNB = sb + XN_BASE + cs * XN_STRIDE;
        MBAR_WAIT(mbF + cs * 8, (t / 3) & 1);

        // ---- MMA1: S[16m x 64n] per warp, k = 64 d, 3 split passes ----
        float accS[8][4];
        #pragma unroll
        for (int j = 0; j < 8; ++j)
            #pragma unroll
            for (int c = 0; c < 4; ++c) accS[j][c] = 0.0f;

        #pragma unroll
        for (int k = 0; k < 4; ++k) {
            uint32_t Ah[4], Al[4];
            const uint32_t offA =
                swz((uint32_t)((k * 16 + l7 + l16h) * 128 + mcol * 2)) + mchunk;
            LDSM_X4_T(Ah, sb + XM_H + offA);
            LDSM_X4_T(Al, sb + XM_L + offA);
            const int drowB = k * 16 + l7 + l8;
            #pragma unroll
            for (int np = 0; np < 4; ++np) {
                uint32_t Bh[4], Bl[4];
                const uint32_t offB =
                    swz((uint32_t)(drowB * 128 + (np * 16 + l16h) * 2)) + nchunk;
                LDSM_X4_T(Bh, XNB + offB);
                LDSM_X4_T(Bl, XNB + IMG + offB);
                hmma(accS[2 * np],     Ah, Bh);
                hmma(accS[2 * np + 1], Ah, Bh + 2);
                hmma(accS[2 * np],     Ah, Bl);
                hmma(accS[2 * np + 1], Ah, Bl + 2);
                hmma(accS[2 * np],     Al, Bh);
                hmma(accS[2 * np + 1], Al, Bh + 2);
            }
        }

        // ---- per k-step: K' = 2^(C*S - tsh) -> fp16 A frags -> MMA2 chunk ----
        // O[16m x 64d] per warp += Kh . Xh, k = 64 n-slice; den via ones column
        #pragma unroll
        for (int ks = 0; ks < 4; ++ks) {
            uint32_t AK[4];
            {
                float e0, e1, e2, e3;
                expk_pair(accS[2 * ks][0], accS[2 * ks][1], ntsA, e0, e1);
                expk_pair(accS[2 * ks][2], accS[2 * ks][3], ntsB, e2, e3);
                AK[0] = pack_f16(e1, e0);
                AK[1] = pack_f16(e3, e2);
                expk_pair(accS[2 * ks + 1][0], accS[2 * ks + 1][1], ntsA, e0, e1);
                expk_pair(accS[2 * ks + 1][2], accS[2 * ks + 1][3], ntsB, e2, e3);
                AK[2] = pack_f16(e1, e0);
                AK[3] = pack_f16(e3, e2);
            }
            hmma(accD, AK, bOne);
            const int kcol = ks * 16 + l8;
            #pragma unroll
            for (int dg = 0; dg < 4; ++dg) {
                const int dd = dg * 16 + l7 + l16h;
                const uint32_t off =
                    swz((uint32_t)(dd * 128 + kcol * 2)) + nchunk;
                uint32_t Bh[4];
                LDSM_X4(Bh, XNB + off);
                hmma(accO[2 * dg],     AK, Bh);
                hmma(accO[2 * dg + 1], AK, Bh + 2);
            }
        }

        // done reading stage cs
        if (l == 0) MBAR_ARRIVE(mbE + cs * 8);
    }

    // ---- den: accD[0]=rows lq, accD[2]=rows lq+8 (all quad lanes equal) ----
    float* sDen = (float*)(smc + SDEN);     // [2][128]
    if (lr == 0) {
        sDen[wn * 128 + mA] = accD[0];
        sDen[wn * 128 + mA + 8] = accD[2];
    }
    __syncthreads();   // all warps done with all tiles; sDen visible

    // ---- partial-O epilogue: scale by STEP/den, write per n-group region ----
    const int mB2 = mA + 8;
    const float scA = STEP / (sDen[mA] + sDen[128 + mA]);
    const float scB = STEP / (sDen[mB2] + sDen[128 + mB2]);
    float* sO = (float*)(smc + wn * 33792);   // [64 d][132 m]
    #pragma unroll
    for (int dg = 0; dg < 4; ++dg)
        #pragma unroll
        for (int s = 0; s < 2; ++s) {
            const float* c = accO[2 * dg + s];
            const int dbase = dg * 16 + s * 8 + 2 * lr;
            sO[dbase * 132 + mA]        = c[0] * scA;
            sO[(dbase + 1) * 132 + mA]  = c[1] * scA;
            sO[dbase * 132 + mB2]       = c[2] * scB;
            sO[(dbase + 1) * 132 + mB2] = c[3] * scB;
        }
    __syncthreads();

    // ---- combine partials + blend with x, store ----
    const float* sO0 = (const float*)(smc);
    const float* sO1 = (const float*)(smc + 33792);
    #pragma unroll
    for (int q = 0; q < 4; ++q) {
        int task = q * THREADS + tid;       // dd(64) x mq(32)
        int dd = task >> 5, mq = task & 31;
        float4 o0 = *(const float4*)&sO0[dd * 132 + mq * 4];
        float4 o1 = *(const float4*)&sO1[dd * 132 + mq * 4];
        float4 x = *(const float4*)(xin + (size_t)dd * N + m0 + mq * 4);
        float4 r;
        r.x = fmaf(1.0f - STEP, x.x, o0.x + o1.x);
        r.y = fmaf(1.0f - STEP, x.y, o0.y + o1.y);
        r.z = fmaf(1.0f - STEP, x.z, o0.z + o1.z);
        r.w = fmaf(1.0f - STEP, x.w, o0.w + o1.w);
        *(float4*)(xout + (size_t)dd * N + m0 + mq * 4) = r;
    }
}

extern "C" void kernel_launch(void* const* d_in, const int* in_sizes, int n_in,
                              void* d_out, int out_size) {
    const float* x = (const float*)d_in[0];
    float* out = (float*)d_out;

    cudaFuncSetAttribute(ms_mma_kernel,
                         cudaFuncAttributeMaxDynamicSharedMemorySize, SMEM_BYTES);

    int copy_total = B * D * N / 4;
    copy_x0_kernel<<<(copy_total + 255) / 256, 256>>>(x, out);

    dim3 grid(NT, B);
    for (int it = 0; it < ITERS; ++it) {
        convert_kernel<<<grid, 256>>>(out, it);
        ms_mma_kernel<<<grid, THREADS, SMEM_BYTES>>>(out, it);
    }
}

// round 9
// speedup vs baseline: 1.6388x; 1.1675x over previous
#include <cuda_runtime.h>
#include <cuda_fp16.h>
#include <cstdint>

// ---------------- problem constants ----------------
constexpr int B = 2;
constexpr int D = 64;
constexpr int N = 96 * 96;      // 9216
constexpr int ITERS = 4;
constexpr float STEP = 0.5f;
constexpr float KBW = 0.3f;
constexpr float LOG2E = 1.4426950408889634f;

constexpr int BM = 128;
constexpr int BN = 128;
constexpr int THREADS = 512;
constexpr int NT = N / BN;      // 72
constexpr int STAGES = 4;

// Tile image: 2 chunks x [64 d][64 pt] fp16, 128B swizzled rows = 16384 B
constexpr int IMG = 16384;

__device__ __align__(16) unsigned char g_xh[(size_t)B * NT * IMG];
__device__ __align__(16) unsigned char g_xl[(size_t)B * NT * IMG];
__device__ float g_tsh[(size_t)B * N];   // per-point log2 shift

// ---------------- smem layout (bytes) ----------------
constexpr int XM_H = 0;              // 16 KB
constexpr int XM_L = 16384;
constexpr int XN_BASE = 32768;       // STAGES x 32 KB (H +0, L +16384)
constexpr int XN_STRIDE = 32768;
constexpr int SDEN = XN_BASE + STAGES * XN_STRIDE;   // 163840; 256 f32
constexpr int MBAR = SDEN + 1024;    // full[4], empty[4], mbx
constexpr int SMEM_BYTES = MBAR + 128;
// epilogue reuse: sO0 f32[64][132] at 0, sO1 at 33792

// ---------------- asm helpers ----------------
__device__ __forceinline__ uint32_t smem_u32(const void* p) {
    uint32_t a;
    asm("{ .reg .u64 t; cvta.to.shared.u64 t, %1; cvt.u32.u64 %0, t; }"
        : "=r"(a) : "l"(p));
    return a;
}

__device__ __forceinline__ uint32_t swz(uint32_t o) {
    return o ^ ((o >> 3) & 0x70);
}

#define MBAR_INIT(mbar, cnt) \
    asm volatile("mbarrier.init.shared.b64 [%0], %1;" :: "r"(mbar), "r"(cnt) : "memory")

#define MBAR_EXPECT_TX(mbar, bytes) \
    asm volatile("mbarrier.arrive.expect_tx.shared.b64 _, [%0], %1;" \
                 :: "r"(mbar), "r"(bytes) : "memory")

#define MBAR_ARRIVE(mbar) \
    asm volatile("mbarrier.arrive.shared.b64 _, [%0];" :: "r"(mbar) : "memory")

#define MBAR_WAIT(mbar, parity) do {                                          \
    uint32_t _m = (mbar), _p = (parity);                                      \
    asm volatile(                                                             \
        "{\n\t.reg .pred P1;\n\t"                                             \
        "WAIT_LOOP_%=:\n\t"                                                   \
        "mbarrier.try_wait.parity.acquire.cta.shared::cta.b64 P1, [%0], %1, 0x989680;\n\t" \
        "@P1 bra.uni WAIT_DONE_%=;\n\t"                                       \
        "bra.uni WAIT_LOOP_%=;\n\t"                                           \
        "WAIT_DONE_%=:\n\t}"                                                  \
        :: "r"(_m), "r"(_p) : "memory");                                      \
} while (0)

__device__ __forceinline__ void bulk_g2s(uint32_t dst, const void* src,
                                         uint32_t bytes, uint32_t mbar) {
    asm volatile(
        "cp.async.bulk.shared::cluster.global.mbarrier::complete_tx::bytes "
        "[%0], [%1], %2, [%3];"
        :: "r"(dst), "l"(__cvta_generic_to_global(src)), "r"(bytes), "r"(mbar)
        : "memory");
}

#define LDSM_X4(r, addr)                                                     \
    asm volatile("ldmatrix.sync.aligned.m8n8.x4.shared.b16 {%0,%1,%2,%3}, [%4];" \
        : "=r"((r)[0]), "=r"((r)[1]), "=r"((r)[2]), "=r"((r)[3]) : "r"(addr))

#define LDSM_X4_T(r, addr)                                                   \
    asm volatile("ldmatrix.sync.aligned.m8n8.x4.trans.shared.b16 {%0,%1,%2,%3}, [%4];" \
        : "=r"((r)[0]), "=r"((r)[1]), "=r"((r)[2]), "=r"((r)[3]) : "r"(addr))

__device__ __forceinline__ void hmma(float* c, const uint32_t* a, const uint32_t* b) {
    asm volatile(
        "mma.sync.aligned.m16n8k16.row.col.f32.f16.f16.f32 "
        "{%0,%1,%2,%3}, {%4,%5,%6,%7}, {%8,%9}, {%0,%1,%2,%3};"
        : "+f"(c[0]), "+f"(c[1]), "+f"(c[2]), "+f"(c[3])
        : "r"(a[0]), "r"(a[1]), "r"(a[2]), "r"(a[3]), "r"(b[0]), "r"(b[1]));
}

// pack two f32 into f16x2 (lo = second arg), saturating to finite
__device__ __forceinline__ uint32_t pack_f16(float hi, float lo) {
    uint32_t r;
    asm("cvt.rn.satfinite.f16x2.f32 %0, %1, %2;" : "=r"(r) : "f"(hi), "f"(lo));
    return r;
}

__device__ __forceinline__ uint32_t pack2h(__half a, __half b) {
    return (uint32_t)__half_as_ushort(a) |
           ((uint32_t)__half_as_ushort(b) << 16);
}

__device__ __forceinline__ void split_pair(float v0, float v1,
                                           uint32_t& hw, uint32_t& lw) {
    __half h0 = __float2half_rn(v0);
    __half h1 = __float2half_rn(v1);
    __half l0 = __float2half_rn(v0 - __half2float(h0));
    __half l1 = __float2half_rn(v1 - __half2float(h1));
    hw = pack2h(h0, h1);
    lw = pack2h(l0, l1);
}

// 2^t via MUFU (otherwise-idle pipe; ~2 ulp)
__device__ __forceinline__ float ex2a(float t) {
    float r;
    asm("ex2.approx.f32 %0, %1;" : "=f"(r) : "f"(t));
    return r;
}

// Copy x_in (B, D, N) into output slice i=0 of (B, ITERS+1, D, N)
__global__ void copy_x0_kernel(const float* __restrict__ x, float* __restrict__ out) {
    int i = blockIdx.x * blockDim.x + threadIdx.x;
    int total = B * D * N / 4;
    if (i < total) {
        int perb = D * N / 4;
        int b = i / perb;
        int r = i - b * perb;
        float4 v = ((const float4*)x)[i];
        ((float4*)out)[(size_t)b * ((ITERS + 1) * D * N / 4) + r] = v;
    }
}

// Convert x slice `it` into hi/lo fp16 swizzled tile images + per-point shift.
__global__ __launch_bounds__(256)
void convert_kernel(const float* __restrict__ out, int it) {
    const int t = blockIdx.x, b = blockIdx.y;
    const int tid = threadIdx.x;
    const float* xs = out + ((size_t)b * (ITERS + 1) + it) * (size_t)(D * N);
    unsigned char* ph = g_xh + (size_t)(b * NT + t) * IMG;
    unsigned char* pl = g_xl + (size_t)(b * NT + t) * IMG;
    #pragma unroll
    for (int q = 0; q < 4; ++q) {
        int task = q * 256 + tid;          // c(2) x d(64) x g(8)
        int c = task >> 9, rem = task & 511;
        int d = rem >> 3, g = rem & 7;
        int n0 = t * BN + c * 64 + g * 8;
        const float4* s = (const float4*)(xs + (size_t)d * N + n0);
        float4 v0 = s[0], v1 = s[1];
        uint32_t hp[4], lp[4];
        split_pair(v0.x, v0.y, hp[0], lp[0]);
        split_pair(v0.z, v0.w, hp[1], lp[1]);
        split_pair(v1.x, v1.y, hp[2], lp[2]);
        split_pair(v1.z, v1.w, hp[3], lp[3]);
        uint32_t off = c * 8192 + swz((uint32_t)(d * 128 + g * 16));
        *(uint4*)(ph + off) = make_uint4(hp[0], hp[1], hp[2], hp[3]);
        *(uint4*)(pl + off) = make_uint4(lp[0], lp[1], lp[2], lp[3]);
    }
    // per-point squared norm -> log2 shift (coalesced across n)
    if (tid < BN) {
        int n = t * BN + tid;
        float s = 0.0f;
        #pragma unroll 8
        for (int d = 0; d < D; ++d) {
            float v = xs[(size_t)d * N + n];
            s = fmaf(v, v, s);
        }
        g_tsh[(size_t)b * N + n] = fmaf(KBW * LOG2E, s, 2.0f);
    }
}

// ---------------- main kernel ----------------
__global__ __launch_bounds__(THREADS, 1)
void ms_mma_kernel(float* __restrict__ out, int it) {
    extern __shared__ unsigned char smc[];
    uint32_t sb = smem_u32(smc);

    const int tid = threadIdx.x;
    const int l = tid & 31;
    const int w = tid >> 5;
    const int wm = w >> 1;       // 8 m-groups of 16 rows
    const int wn = w & 1;        // 2 n-groups of 64 cols

    const int b = blockIdx.y;
    const int m0 = blockIdx.x * BM;
    const float* __restrict__ xin = out + ((size_t)b * (ITERS + 1) + it) * (size_t)(D * N);
    float* __restrict__ xout = (float*)xin + (size_t)D * N;

    const int l7 = l & 7, l8 = l & 8, l16h = (l & 16) >> 1, lq = l >> 2, lr = l & 3;

    const uint32_t mbF = sb + MBAR;            // full[4] at +0..+24
    const uint32_t mbE = sb + MBAR + 32;       // empty[4]
    const uint32_t mbx = sb + MBAR + 64;

    // ---- prologue ----
    if (tid == 0) {
        #pragma unroll
        for (int s = 0; s < STAGES; ++s) {
            MBAR_INIT(mbF + s * 8, 1);
            MBAR_INIT(mbE + s * 8, 16);
        }
        MBAR_INIT(mbx, 1);
    }
    __syncthreads();
    const unsigned char* gh = g_xh + (size_t)b * NT * IMG;
    const unsigned char* gl = g_xl + (size_t)b * NT * IMG;
    if (tid == 0) {
        MBAR_EXPECT_TX(mbx, 2 * IMG);
        bulk_g2s(sb + XM_H, gh + (size_t)blockIdx.x * IMG, IMG, mbx);
        bulk_g2s(sb + XM_L, gl + (size_t)blockIdx.x * IMG, IMG, mbx);
        #pragma unroll
        for (int u = 0; u < 3; ++u) {
            MBAR_EXPECT_TX(mbF + u * 8, 2 * IMG);
            bulk_g2s(sb + XN_BASE + u * XN_STRIDE, gh + (size_t)u * IMG, IMG, mbF + u * 8);
            bulk_g2s(sb + XN_BASE + u * XN_STRIDE + IMG, gl + (size_t)u * IMG, IMG, mbF + u * 8);
        }
    }

    // per-warp address components
    const int mchunk = (wm >> 2) * 8192;
    const int mcol = (wm & 3) * 16 + l8;
    const int nchunk = wn * 8192;

    // per-thread K-column shifts (rows mA, mA+8)
    const int mA = wm * 16 + lq;
    const float ntsA = -g_tsh[(size_t)b * N + m0 + mA];
    const float ntsB = -g_tsh[(size_t)b * N + m0 + mA + 8];
    const float C = KBW * LOG2E;

    const uint32_t oneh = 0x3C003C00u;   // fp16 {1,1}
    const uint32_t bOne[2] = {oneh, oneh};

    float accO[8][4];
    #pragma unroll
    for (int j = 0; j < 8; ++j)
        #pragma unroll
        for (int c = 0; c < 4; ++c) accO[j][c] = 0.0f;
    float accD[4] = {0.0f, 0.0f, 0.0f, 0.0f};

    MBAR_WAIT(mbx, 0);

    for (int t = 0; t < NT; ++t) {
        // producer: prefetch tile t+3 into stage (t+3)%STAGES
        if (tid == 0) {
            const int u = t + 3;
            if (u < NT) {
                const int us = u & 3, uj = u >> 2;
                if (u >= STAGES) MBAR_WAIT(mbE + us * 8, (uj - 1) & 1);
                MBAR_EXPECT_TX(mbF + us * 8, 2 * IMG);
                const uint32_t nb = sb + XN_BASE + us * XN_STRIDE;
                bulk_g2s(nb, gh + (size_t)u * IMG, IMG, mbF + us * 8);
                bulk_g2s(nb + IMG, gl + (size_t)u * IMG, IMG, mbF + us * 8);
            }
        }
        const int cs = t & 3;
        const uint32_t XNB = sb + XN_BASE + cs * XN_STRIDE;
        MBAR_WAIT(mbF + cs * 8, (t >> 2) & 1);

        // ---- MMA1: S[16m x 64n] per warp, k = 64 d, 3 split passes ----
        float accS[8][4];
        #pragma unroll
        for (int j = 0; j < 8; ++j)
            #pragma unroll
            for (int c = 0; c < 4; ++c) accS[j][c] = 0.0f;

        #pragma unroll
        for (int k = 0; k < 4; ++k) {
            uint32_t Ah[4], Al[4];
            const uint32_t offA =
                swz((uint32_t)((k * 16 + l7 + l16h) * 128 + mcol * 2)) + mchunk;
            LDSM_X4_T(Ah, sb + XM_H + offA);
            LDSM_X4_T(Al, sb + XM_L + offA);
            const int drowB = k * 16 + l7 + l8;
            #pragma unroll
            for (int np = 0; np < 4; ++np) {
                uint32_t Bh[4], Bl[4];
                const uint32_t offB =
                    swz((uint32_t)(drowB * 128 + (np * 16 + l16h) * 2)) + nchunk;
                LDSM_X4_T(Bh, XNB + offB);
                LDSM_X4_T(Bl, XNB + IMG + offB);
                hmma(accS[2 * np],     Ah, Bh);
                hmma(accS[2 * np + 1], Ah, Bh + 2);
                hmma(accS[2 * np],     Ah, Bl);
                hmma(accS[2 * np + 1], Ah, Bl + 2);
                hmma(accS[2 * np],     Al, Bh);
                hmma(accS[2 * np + 1], Al, Bh + 2);
            }
        }

        // ---- per k-step: K' = 2^(C*S - tsh) via MUFU -> fp16 A -> MMA2 ----
        // O[16m x 64d] per warp += Kh . Xh, k = 64 n-slice; den via ones column
        #pragma unroll
        for (int ks = 0; ks < 4; ++ks) {
            uint32_t AK[4];
            #pragma unroll
            for (int h = 0; h < 2; ++h) {
                const float* s = accS[2 * ks + h];
                float e0 = ex2a(fmaf(s[0], C, ntsA));
                float e1 = ex2a(fmaf(s[1], C, ntsA));
                float e2 = ex2a(fmaf(s[2], C, ntsB));
                float e3 = ex2a(fmaf(s[3], C, ntsB));
                AK[2 * h]     = pack_f16(e1, e0);
                AK[2 * h + 1] = pack_f16(e3, e2);
            }
            hmma(accD, AK, bOne);
            const int kcol = ks * 16 + l8;
            #pragma unroll
            for (int dg = 0; dg < 4; ++dg) {
                const int dd = dg * 16 + l7 + l16h;
                const uint32_t off =
                    swz((uint32_t)(dd * 128 + kcol * 2)) + nchunk;
                uint32_t Bh[4];
                LDSM_X4(Bh, XNB + off);
                hmma(accO[2 * dg],     AK, Bh);
                hmma(accO[2 * dg + 1], AK, Bh + 2);
            }
        }

        // done reading stage cs
        if (l == 0) MBAR_ARRIVE(mbE + cs * 8);
    }

    // ---- den: accD[0]=rows lq, accD[2]=rows lq+8 (all quad lanes equal) ----
    float* sDen = (float*)(smc + SDEN);     // [2][128]
    if (lr == 0) {
        sDen[wn * 128 + mA] = accD[0];
        sDen[wn * 128 + mA + 8] = accD[2];
    }
    __syncthreads();   // all warps done with all tiles; sDen visible

    // ---- partial-O epilogue: scale by STEP/den, write per n-group region ----
    const int mB2 = mA + 8;
    const float scA = STEP / (sDen[mA] + sDen[128 + mA]);
    const float scB = STEP / (sDen[mB2] + sDen[128 + mB2]);
    float* sO = (float*)(smc + wn * 33792);   // [64 d][132 m]
    #pragma unroll
    for (int dg = 0; dg < 4; ++dg)
        #pragma unroll
        for (int s = 0; s < 2; ++s) {
            const float* c = accO[2 * dg + s];
            const int dbase = dg * 16 + s * 8 + 2 * lr;
            sO[dbase * 132 + mA]        = c[0] * scA;
            sO[(dbase + 1) * 132 + mA]  = c[1] * scA;
            sO[dbase * 132 + mB2]       = c[2] * scB;
            sO[(dbase + 1) * 132 + mB2] = c[3] * scB;
        }
    __syncthreads();

    // ---- combine partials + blend with x, store ----
    const float* sO0 = (const float*)(smc);
    const float* sO1 = (const float*)(smc + 33792);
    #pragma unroll
    for (int q = 0; q < 4; ++q) {
        int task = q * THREADS + tid;       // dd(64) x mq(32)
        int dd = task >> 5, mq = task & 31;
        float4 o0 = *(const float4*)&sO0[dd * 132 + mq * 4];
        float4 o1 = *(const float4*)&sO1[dd * 132 + mq * 4];
        float4 x = *(const float4*)(xin + (size_t)dd * N + m0 + mq * 4);
        float4 r;
        r.x = fmaf(1.0f - STEP, x.x, o0.x + o1.x);
        r.y = fmaf(1.0f - STEP, x.y, o0.y + o1.y);
        r.z = fmaf(1.0f - STEP, x.z, o0.z + o1.z);
        r.w = fmaf(1.0f - STEP, x.w, o0.w + o1.w);
        *(float4*)(xout + (size_t)dd * N + m0 + mq * 4) = r;
    }
}

extern "C" void kernel_launch(void* const* d_in, const int* in_sizes, int n_in,
                              void* d_out, int out_size) {
    const float* x = (const float*)d_in[0];
    float* out = (float*)d_out;

    cudaFuncSetAttribute(ms_mma_kernel,
                         cudaFuncAttributeMaxDynamicSharedMemorySize, SMEM_BYTES);

    int copy_total = B * D * N / 4;
    copy_x0_kernel<<<(copy_total + 255) / 256, 256>>>(x, out);

    dim3 grid(NT, B);
    for (int it = 0; it < ITERS; ++it) {
        convert_kernel<<<grid, 256>>>(out, it);
        ms_mma_kernel<<<grid, THREADS, SMEM_BYTES>>>(out, it);
    }
}

// round 10
// speedup vs baseline: 2.0208x; 1.2331x over previous
#include <cuda_runtime.h>
#include <cuda_fp16.h>
#include <cstdint>

// ---------------- problem constants ----------------
constexpr int B = 2;
constexpr int D = 64;
constexpr int N = 96 * 96;      // 9216
constexpr int ITERS = 4;
constexpr float STEP = 0.5f;
constexpr float KBW = 0.3f;
constexpr float LOG2E = 1.4426950408889634f;

constexpr int BM = 128;
constexpr int BN = 128;
constexpr int THREADS = 512;
constexpr int NT = N / BN;      // 72
constexpr int STAGES = 8;

// Tile image: 2 chunks x [64 d][64 pt] fp16, 128B swizzled rows = 16384 B
constexpr int IMG = 16384;

__device__ __align__(16) unsigned char g_xh[(size_t)B * NT * IMG];
__device__ __align__(16) unsigned char g_xl[(size_t)B * NT * IMG];
__device__ float g_tsh[(size_t)B * N];   // per-point log2 shift

// ---------------- smem layout (bytes) ----------------
constexpr int XM_H = 0;              // 16 KB
constexpr int XM_L = 16384;
constexpr int XN_BASE = 32768;       // STAGES x 16 KB (hi only)
constexpr int XN_STRIDE = 16384;
constexpr int SDEN = XN_BASE + STAGES * XN_STRIDE;   // 163840; 256 f32
constexpr int MBAR = SDEN + 1024;    // full[8], empty[8], mbx
constexpr int SMEM_BYTES = MBAR + 256;
// epilogue reuse: sO0 f32[64][132] at 0, sO1 at 33792

// ---------------- asm helpers ----------------
__device__ __forceinline__ uint32_t smem_u32(const void* p) {
    uint32_t a;
    asm("{ .reg .u64 t; cvta.to.shared.u64 t, %1; cvt.u32.u64 %0, t; }"
        : "=r"(a) : "l"(p));
    return a;
}

__device__ __forceinline__ uint32_t swz(uint32_t o) {
    return o ^ ((o >> 3) & 0x70);
}

#define MBAR_INIT(mbar, cnt) \
    asm volatile("mbarrier.init.shared.b64 [%0], %1;" :: "r"(mbar), "r"(cnt) : "memory")

#define MBAR_EXPECT_TX(mbar, bytes) \
    asm volatile("mbarrier.arrive.expect_tx.shared.b64 _, [%0], %1;" \
                 :: "r"(mbar), "r"(bytes) : "memory")

#define MBAR_ARRIVE(mbar) \
    asm volatile("mbarrier.arrive.shared.b64 _, [%0];" :: "r"(mbar) : "memory")

#define MBAR_WAIT(mbar, parity) do {                                          \
    uint32_t _m = (mbar), _p = (parity);                                      \
    asm volatile(                                                             \
        "{\n\t.reg .pred P1;\n\t"                                             \
        "WAIT_LOOP_%=:\n\t"                                                   \
        "mbarrier.try_wait.parity.acquire.cta.shared::cta.b64 P1, [%0], %1, 0x989680;\n\t" \
        "@P1 bra.uni WAIT_DONE_%=;\n\t"                                       \
        "bra.uni WAIT_LOOP_%=;\n\t"                                           \
        "WAIT_DONE_%=:\n\t}"                                                  \
        :: "r"(_m), "r"(_p) : "memory");                                      \
} while (0)

__device__ __forceinline__ void bulk_g2s(uint32_t dst, const void* src,
                                         uint32_t bytes, uint32_t mbar) {
    asm volatile(
        "cp.async.bulk.shared::cluster.global.mbarrier::complete_tx::bytes "
        "[%0], [%1], %2, [%3];"
        :: "r"(dst), "l"(__cvta_generic_to_global(src)), "r"(bytes), "r"(mbar)
        : "memory");
}

#define LDSM_X4(r, addr)                                                     \
    asm volatile("ldmatrix.sync.aligned.m8n8.x4.shared.b16 {%0,%1,%2,%3}, [%4];" \
        : "=r"((r)[0]), "=r"((r)[1]), "=r"((r)[2]), "=r"((r)[3]) : "r"(addr))

#define LDSM_X4_T(r, addr)                                                   \
    asm volatile("ldmatrix.sync.aligned.m8n8.x4.trans.shared.b16 {%0,%1,%2,%3}, [%4];" \
        : "=r"((r)[0]), "=r"((r)[1]), "=r"((r)[2]), "=r"((r)[3]) : "r"(addr))

__device__ __forceinline__ void hmma(float* c, const uint32_t* a, const uint32_t* b) {
    asm volatile(
        "mma.sync.aligned.m16n8k16.row.col.f32.f16.f16.f32 "
        "{%0,%1,%2,%3}, {%4,%5,%6,%7}, {%8,%9}, {%0,%1,%2,%3};"
        : "+f"(c[0]), "+f"(c[1]), "+f"(c[2]), "+f"(c[3])
        : "r"(a[0]), "r"(a[1]), "r"(a[2]), "r"(a[3]), "r"(b[0]), "r"(b[1]));
}

// pack two f32 into f16x2 (lo = second arg), saturating to finite
__device__ __forceinline__ uint32_t pack_f16(float hi, float lo) {
    uint32_t r;
    asm("cvt.rn.satfinite.f16x2.f32 %0, %1, %2;" : "=r"(r) : "f"(hi), "f"(lo));
    return r;
}

__device__ __forceinline__ uint32_t pack2h(__half a, __half b) {
    return (uint32_t)__half_as_ushort(a) |
           ((uint32_t)__half_as_ushort(b) << 16);
}

__device__ __forceinline__ void split_pair(float v0, float v1,
                                           uint32_t& hw, uint32_t& lw) {
    __half h0 = __float2half_rn(v0);
    __half h1 = __float2half_rn(v1);
    __half l0 = __float2half_rn(v0 - __half2float(h0));
    __half l1 = __float2half_rn(v1 - __half2float(h1));
    hw = pack2h(h0, h1);
    lw = pack2h(l0, l1);
}

// 2^t via MUFU (otherwise-idle pipe; ~2 ulp)
__device__ __forceinline__ float ex2a(float t) {
    float r;
    asm("ex2.approx.f32 %0, %1;" : "=f"(r) : "f"(t));
    return r;
}

// Copy x_in (B, D, N) into output slice i=0 of (B, ITERS+1, D, N)
__global__ void copy_x0_kernel(const float* __restrict__ x, float* __restrict__ out) {
    int i = blockIdx.x * blockDim.x + threadIdx.x;
    int total = B * D * N / 4;
    if (i < total) {
        int perb = D * N / 4;
        int b = i / perb;
        int r = i - b * perb;
        float4 v = ((const float4*)x)[i];
        ((float4*)out)[(size_t)b * ((ITERS + 1) * D * N / 4) + r] = v;
    }
}

// Convert x slice `it` into hi/lo fp16 swizzled tile images + per-point shift.
__global__ __launch_bounds__(256)
void convert_kernel(const float* __restrict__ out, int it) {
    const int t = blockIdx.x, b = blockIdx.y;
    const int tid = threadIdx.x;
    const float* xs = out + ((size_t)b * (ITERS + 1) + it) * (size_t)(D * N);
    unsigned char* ph = g_xh + (size_t)(b * NT + t) * IMG;
    unsigned char* pl = g_xl + (size_t)(b * NT + t) * IMG;
    #pragma unroll
    for (int q = 0; q < 4; ++q) {
        int task = q * 256 + tid;          // c(2) x d(64) x g(8)
        int c = task >> 9, rem = task & 511;
        int d = rem >> 3, g = rem & 7;
        int n0 = t * BN + c * 64 + g * 8;
        const float4* s = (const float4*)(xs + (size_t)d * N + n0);
        float4 v0 = s[0], v1 = s[1];
        uint32_t hp[4], lp[4];
        split_pair(v0.x, v0.y, hp[0], lp[0]);
        split_pair(v0.z, v0.w, hp[1], lp[1]);
        split_pair(v1.x, v1.y, hp[2], lp[2]);
        split_pair(v1.z, v1.w, hp[3], lp[3]);
        uint32_t off = c * 8192 + swz((uint32_t)(d * 128 + g * 16));
        *(uint4*)(ph + off) = make_uint4(hp[0], hp[1], hp[2], hp[3]);
        *(uint4*)(pl + off) = make_uint4(lp[0], lp[1], lp[2], lp[3]);
    }
    // per-point squared norm -> log2 shift (coalesced across n)
    if (tid < BN) {
        int n = t * BN + tid;
        float s = 0.0f;
        #pragma unroll 8
        for (int d = 0; d < D; ++d) {
            float v = xs[(size_t)d * N + n];
            s = fmaf(v, v, s);
        }
        g_tsh[(size_t)b * N + n] = fmaf(KBW * LOG2E, s, 2.0f);
    }
}

// ---------------- main kernel ----------------
__global__ __launch_bounds__(THREADS, 1)
void ms_mma_kernel(float* __restrict__ out, int it) {
    extern __shared__ unsigned char smc[];
    uint32_t sb = smem_u32(smc);

    const int tid = threadIdx.x;
    const int l = tid & 31;
    const int w = tid >> 5;
    const int wm = w >> 1;       // 8 m-groups of 16 rows
    const int wn = w & 1;        // 2 n-groups of 64 cols

    const int b = blockIdx.y;
    const int m0 = blockIdx.x * BM;
    const float* __restrict__ xin = out + ((size_t)b * (ITERS + 1) + it) * (size_t)(D * N);
    float* __restrict__ xout = (float*)xin + (size_t)D * N;

    const int l7 = l & 7, l8 = l & 8, l16h = (l & 16) >> 1, lq = l >> 2, lr = l & 3;

    const uint32_t mbF = sb + MBAR;            // full[8]
    const uint32_t mbE = sb + MBAR + 64;       // empty[8]
    const uint32_t mbx = sb + MBAR + 128;

    // ---- prologue ----
    if (tid == 0) {
        #pragma unroll
        for (int s = 0; s < STAGES; ++s) {
            MBAR_INIT(mbF + s * 8, 1);
            MBAR_INIT(mbE + s * 8, 16);
        }
        MBAR_INIT(mbx, 1);
    }
    __syncthreads();
    const unsigned char* gh = g_xh + (size_t)b * NT * IMG;
    const unsigned char* gl = g_xl + (size_t)b * NT * IMG;
    if (tid == 0) {
        MBAR_EXPECT_TX(mbx, 2 * IMG);
        bulk_g2s(sb + XM_H, gh + (size_t)blockIdx.x * IMG, IMG, mbx);
        bulk_g2s(sb + XM_L, gl + (size_t)blockIdx.x * IMG, IMG, mbx);
        #pragma unroll
        for (int u = 0; u < 6; ++u) {
            MBAR_EXPECT_TX(mbF + u * 8, IMG);
            bulk_g2s(sb + XN_BASE + u * XN_STRIDE, gh + (size_t)u * IMG, IMG, mbF + u * 8);
        }
    }

    // per-warp address components
    const int mchunk = (wm >> 2) * 8192;
    const int mcol = (wm & 3) * 16 + l8;
    const int nchunk = wn * 8192;

    // per-thread K-column shifts (rows mA, mA+8)
    const int mA = wm * 16 + lq;
    const float ntsA = -g_tsh[(size_t)b * N + m0 + mA];
    const float ntsB = -g_tsh[(size_t)b * N + m0 + mA + 8];
    const float C = KBW * LOG2E;

    const uint32_t oneh = 0x3C003C00u;   // fp16 {1,1}
    const uint32_t bOne[2] = {oneh, oneh};

    float accO[8][4];
    #pragma unroll
    for (int j = 0; j < 8; ++j)
        #pragma unroll
        for (int c = 0; c < 4; ++c) accO[j][c] = 0.0f;
    float accD[4] = {0.0f, 0.0f, 0.0f, 0.0f};

    MBAR_WAIT(mbx, 0);

    for (int t = 0; t < NT; ++t) {
        // producer: prefetch tile t+6 into stage (t+6)%STAGES
        if (tid == 0) {
            const int u = t + 6;
            if (u < NT) {
                const int us = u & 7, uj = u >> 3;
                if (u >= STAGES) MBAR_WAIT(mbE + us * 8, (uj - 1) & 1);
                MBAR_EXPECT_TX(mbF + us * 8, IMG);
                bulk_g2s(sb + XN_BASE + us * XN_STRIDE, gh + (size_t)u * IMG,
                         IMG, mbF + us * 8);
            }
        }
        const int cs = t & 7;
        const uint32_t XNB = sb + XN_BASE + cs * XN_STRIDE;
        MBAR_WAIT(mbF + cs * 8, (t >> 3) & 1);

        // ---- MMA1: S[16m x 64n] = (Xmh+Xml) . Xnh, k-concat single pass ----
        float accS[8][4];
        #pragma unroll
        for (int j = 0; j < 8; ++j)
            #pragma unroll
            for (int c = 0; c < 4; ++c) accS[j][c] = 0.0f;

        #pragma unroll
        for (int k = 0; k < 4; ++k) {
            uint32_t Ah[4], Al[4];
            const uint32_t offA =
                swz((uint32_t)((k * 16 + l7 + l16h) * 128 + mcol * 2)) + mchunk;
            LDSM_X4_T(Ah, sb + XM_H + offA);
            LDSM_X4_T(Al, sb + XM_L + offA);
            const int drowB = k * 16 + l7 + l8;
            #pragma unroll
            for (int np = 0; np < 4; ++np) {
                uint32_t Bh[4];
                const uint32_t offB =
                    swz((uint32_t)(drowB * 128 + (np * 16 + l16h) * 2)) + nchunk;
                LDSM_X4_T(Bh, XNB + offB);
                hmma(accS[2 * np],     Ah, Bh);
                hmma(accS[2 * np + 1], Ah, Bh + 2);
                hmma(accS[2 * np],     Al, Bh);
                hmma(accS[2 * np + 1], Al, Bh + 2);
            }
        }

        // ---- per k-step: K' = 2^(C*S - tsh) via MUFU -> fp16 A -> MMA2 ----
        // O[16m x 64d] per warp += Kh . Xh, k = 64 n-slice; den via ones column
        #pragma unroll
        for (int ks = 0; ks < 4; ++ks) {
            uint32_t AK[4];
            #pragma unroll
            for (int h = 0; h < 2; ++h) {
                const float* s = accS[2 * ks + h];
                float e0 = ex2a(fmaf(s[0], C, ntsA));
                float e1 = ex2a(fmaf(s[1], C, ntsA));
                float e2 = ex2a(fmaf(s[2], C, ntsB));
                float e3 = ex2a(fmaf(s[3], C, ntsB));
                AK[2 * h]     = pack_f16(e1, e0);
                AK[2 * h + 1] = pack_f16(e3, e2);
            }
            hmma(accD, AK, bOne);
            const int kcol = ks * 16 + l8;
            #pragma unroll
            for (int dg = 0; dg < 4; ++dg) {
                const int dd = dg * 16 + l7 + l16h;
                const uint32_t off =
                    swz((uint32_t)(dd * 128 + kcol * 2)) + nchunk;
                uint32_t Bh[4];
                LDSM_X4(Bh, XNB + off);
                hmma(accO[2 * dg],     AK, Bh);
                hmma(accO[2 * dg + 1], AK, Bh + 2);
            }
        }

        // done reading stage cs
        if (l == 0) MBAR_ARRIVE(mbE + cs * 8);
    }

    // ---- den: accD[0]=rows lq, accD[2]=rows lq+8 (all quad lanes equal) ----
    float* sDen = (float*)(smc + SDEN);     // [2][128]
    if (lr == 0) {
        sDen[wn * 128 + mA] = accD[0];
        sDen[wn * 128 + mA + 8] = accD[2];
    }
    __syncthreads();   // all warps done with all tiles; sDen visible

    // ---- partial-O epilogue: scale by STEP/den, write per n-group region ----
    const int mB2 = mA + 8;
    const float scA = STEP / (sDen[mA] + sDen[128 + mA]);
    const float scB = STEP / (sDen[mB2] + sDen[128 + mB2]);
    float* sO = (float*)(smc + wn * 33792);   // [64 d][132 m]
    #pragma unroll
    for (int dg = 0; dg < 4; ++dg)
        #pragma unroll
        for (int s = 0; s < 2; ++s) {
            const float* c = accO[2 * dg + s];
            const int dbase = dg * 16 + s * 8 + 2 * lr;
            sO[dbase * 132 + mA]        = c[0] * scA;
            sO[(dbase + 1) * 132 + mA]  = c[1] * scA;
            sO[dbase * 132 + mB2]       = c[2] * scB;
            sO[(dbase + 1) * 132 + mB2] = c[3] * scB;
        }
    __syncthreads();

    // ---- combine partials + blend with x, store ----
    const float* sO0 = (const float*)(smc);
    const float* sO1 = (const float*)(smc + 33792);
    #pragma unroll
    for (int q = 0; q < 4; ++q) {
        int task = q * THREADS + tid;       // dd(64) x mq(32)
        int dd = task >> 5, mq = task & 31;
        float4 o0 = *(const float4*)&sO0[dd * 132 + mq * 4];
        float4 o1 = *(const float4*)&sO1[dd * 132 + mq * 4];
        float4 x = *(const float4*)(xin + (size_t)dd * N + m0 + mq * 4);
        float4 r;
        r.x = fmaf(1.0f - STEP, x.x, o0.x + o1.x);
        r.y = fmaf(1.0f - STEP, x.y, o0.y + o1.y);
        r.z = fmaf(1.0f - STEP, x.z, o0.z + o1.z);
        r.w = fmaf(1.0f - STEP, x.w, o0.w + o1.w);
        *(float4*)(xout + (size_t)dd * N + m0 + mq * 4) = r;
    }
}

extern "C" void kernel_launch(void* const* d_in, const int* in_sizes, int n_in,
                              void* d_out, int out_size) {
    const float* x = (const float*)d_in[0];
    float* out = (float*)d_out;

    cudaFuncSetAttribute(ms_mma_kernel,
                         cudaFuncAttributeMaxDynamicSharedMemorySize, SMEM_BYTES);

    int copy_total = B * D * N / 4;
    copy_x0_kernel<<<(copy_total + 255) / 256, 256>>>(x, out);

    dim3 grid(NT, B);
    for (int it = 0; it < ITERS; ++it) {
        convert_kernel<<<grid, 256>>>(out, it);
        ms_mma_kernel<<<grid, THREADS, SMEM_BYTES>>>(out, it);
    }
}

// round 11
// speedup vs baseline: 2.7037x; 1.3379x over previous
#include <cuda_runtime.h>
#include <cuda_fp16.h>
#include <cstdint>

// ---------------- problem constants ----------------
constexpr int B = 2;
constexpr int D = 64;
constexpr int N = 96 * 96;      // 9216
constexpr int ITERS = 4;
constexpr float STEP = 0.5f;
constexpr float KBW = 0.3f;
constexpr float LOG2E = 1.4426950408889634f;

constexpr int BM = 128;
constexpr int BN = 128;
constexpr int THREADS = 512;
constexpr int NT = N / BN;      // 72
constexpr int STAGES = 8;

// Tile image: 2 chunks x [64 d][64 pt] fp16, 128B swizzled rows = 16384 B
constexpr int IMG = 16384;

__device__ __align__(16) unsigned char g_xh[(size_t)B * NT * IMG];
__device__ float g_tsh[(size_t)B * N];   // per-point log2 shift

// ---------------- smem layout (bytes) ----------------
constexpr int XM_H = 0;              // 16 KB
constexpr int XN_BASE = 16384;       // STAGES x 16 KB (hi only)
constexpr int XN_STRIDE = 16384;
constexpr int SDEN = XN_BASE + STAGES * XN_STRIDE;   // 147456; 256 f32
constexpr int MBAR = SDEN + 1024;    // full[8], empty[8], mbx
constexpr int SMEM_BYTES = MBAR + 256;
// epilogue reuse: sO0 f32[64][132] at 0, sO1 at 33792

// ---------------- asm helpers ----------------
__device__ __forceinline__ uint32_t smem_u32(const void* p) {
    uint32_t a;
    asm("{ .reg .u64 t; cvta.to.shared.u64 t, %1; cvt.u32.u64 %0, t; }"
        : "=r"(a) : "l"(p));
    return a;
}

__device__ __forceinline__ uint32_t swz(uint32_t o) {
    return o ^ ((o >> 3) & 0x70);
}

#define MBAR_INIT(mbar, cnt) \
    asm volatile("mbarrier.init.shared.b64 [%0], %1;" :: "r"(mbar), "r"(cnt) : "memory")

#define MBAR_EXPECT_TX(mbar, bytes) \
    asm volatile("mbarrier.arrive.expect_tx.shared.b64 _, [%0], %1;" \
                 :: "r"(mbar), "r"(bytes) : "memory")

#define MBAR_ARRIVE(mbar) \
    asm volatile("mbarrier.arrive.shared.b64 _, [%0];" :: "r"(mbar) : "memory")

#define MBAR_WAIT(mbar, parity) do {                                          \
    uint32_t _m = (mbar), _p = (parity);                                      \
    asm volatile(                                                             \
        "{\n\t.reg .pred P1;\n\t"                                             \
        "WAIT_LOOP_%=:\n\t"                                                   \
        "mbarrier.try_wait.parity.acquire.cta.shared::cta.b64 P1, [%0], %1, 0x989680;\n\t" \
        "@P1 bra.uni WAIT_DONE_%=;\n\t"                                       \
        "bra.uni WAIT_LOOP_%=;\n\t"                                           \
        "WAIT_DONE_%=:\n\t}"                                                  \
        :: "r"(_m), "r"(_p) : "memory");                                      \
} while (0)

__device__ __forceinline__ void bulk_g2s(uint32_t dst, const void* src,
                                         uint32_t bytes, uint32_t mbar) {
    asm volatile(
        "cp.async.bulk.shared::cluster.global.mbarrier::complete_tx::bytes "
        "[%0], [%1], %2, [%3];"
        :: "r"(dst), "l"(__cvta_generic_to_global(src)), "r"(bytes), "r"(mbar)
        : "memory");
}

#define LDSM_X4(r, addr)                                                     \
    asm volatile("ldmatrix.sync.aligned.m8n8.x4.shared.b16 {%0,%1,%2,%3}, [%4];" \
        : "=r"((r)[0]), "=r"((r)[1]), "=r"((r)[2]), "=r"((r)[3]) : "r"(addr))

#define LDSM_X4_T(r, addr)                                                   \
    asm volatile("ldmatrix.sync.aligned.m8n8.x4.trans.shared.b16 {%0,%1,%2,%3}, [%4];" \
        : "=r"((r)[0]), "=r"((r)[1]), "=r"((r)[2]), "=r"((r)[3]) : "r"(addr))

__device__ __forceinline__ void hmma(float* c, const uint32_t* a, const uint32_t* b) {
    asm volatile(
        "mma.sync.aligned.m16n8k16.row.col.f32.f16.f16.f32 "
        "{%0,%1,%2,%3}, {%4,%5,%6,%7}, {%8,%9}, {%0,%1,%2,%3};"
        : "+f"(c[0]), "+f"(c[1]), "+f"(c[2]), "+f"(c[3])
        : "r"(a[0]), "r"(a[1]), "r"(a[2]), "r"(a[3]), "r"(b[0]), "r"(b[1]));
}

// pack two f32 into f16x2 (lo = second arg), saturating to finite
__device__ __forceinline__ uint32_t pack_f16(float hi, float lo) {
    uint32_t r;
    asm("cvt.rn.satfinite.f16x2.f32 %0, %1, %2;" : "=r"(r) : "f"(hi), "f"(lo));
    return r;
}

__device__ __forceinline__ uint32_t pack2h(__half a, __half b) {
    return (uint32_t)__half_as_ushort(a) |
           ((uint32_t)__half_as_ushort(b) << 16);
}

// 2^t via MUFU (otherwise-idle pipe; ~2 ulp)
__device__ __forceinline__ float ex2a(float t) {
    float r;
    asm("ex2.approx.f32 %0, %1;" : "=f"(r) : "f"(t));
    return r;
}

// Copy x_in (B, D, N) into output slice i=0 of (B, ITERS+1, D, N)
__global__ void copy_x0_kernel(const float* __restrict__ x, float* __restrict__ out) {
    int i = blockIdx.x * blockDim.x + threadIdx.x;
    int total = B * D * N / 4;
    if (i < total) {
        int perb = D * N / 4;
        int b = i / perb;
        int r = i - b * perb;
        float4 v = ((const float4*)x)[i];
        ((float4*)out)[(size_t)b * ((ITERS + 1) * D * N / 4) + r] = v;
    }
}

// Convert x slice `it` into fp16 swizzled tile images + per-point shift.
__global__ __launch_bounds__(256)
void convert_kernel(const float* __restrict__ out, int it) {
    const int t = blockIdx.x, b = blockIdx.y;
    const int tid = threadIdx.x;
    const float* xs = out + ((size_t)b * (ITERS + 1) + it) * (size_t)(D * N);
    unsigned char* ph = g_xh + (size_t)(b * NT + t) * IMG;
    #pragma unroll
    for (int q = 0; q < 4; ++q) {
        int task = q * 256 + tid;          // c(2) x d(64) x g(8)
        int c = task >> 9, rem = task & 511;
        int d = rem >> 3, g = rem & 7;
        int n0 = t * BN + c * 64 + g * 8;
        const float4* s = (const float4*)(xs + (size_t)d * N + n0);
        float4 v0 = s[0], v1 = s[1];
        uint32_t hp[4];
        hp[0] = pack_f16(v0.y, v0.x);
        hp[1] = pack_f16(v0.w, v0.z);
        hp[2] = pack_f16(v1.y, v1.x);
        hp[3] = pack_f16(v1.w, v1.z);
        uint32_t off = c * 8192 + swz((uint32_t)(d * 128 + g * 16));
        *(uint4*)(ph + off) = make_uint4(hp[0], hp[1], hp[2], hp[3]);
    }
    // per-point squared norm -> log2 shift (coalesced across n)
    if (tid < BN) {
        int n = t * BN + tid;
        float s = 0.0f;
        #pragma unroll 8
        for (int d = 0; d < D; ++d) {
            float v = xs[(size_t)d * N + n];
            s = fmaf(v, v, s);
        }
        g_tsh[(size_t)b * N + n] = fmaf(KBW * LOG2E, s, 2.0f);
    }
}

// ---------------- main kernel ----------------
__global__ __launch_bounds__(THREADS, 1)
void ms_mma_kernel(float* __restrict__ out, int it) {
    extern __shared__ unsigned char smc[];
    uint32_t sb = smem_u32(smc);

    const int tid = threadIdx.x;
    const int l = tid & 31;
    const int w = tid >> 5;
    const int wm = w >> 1;       // 8 m-groups of 16 rows
    const int wn = w & 1;        // 2 n-groups of 64 cols

    const int b = blockIdx.y;
    const int m0 = blockIdx.x * BM;
    const float* __restrict__ xin = out + ((size_t)b * (ITERS + 1) + it) * (size_t)(D * N);
    float* __restrict__ xout = (float*)xin + (size_t)D * N;

    const int l7 = l & 7, l8 = l & 8, l16h = (l & 16) >> 1, lq = l >> 2, lr = l & 3;

    const uint32_t mbF = sb + MBAR;            // full[8]
    const uint32_t mbE = sb + MBAR + 64;       // empty[8]
    const uint32_t mbx = sb + MBAR + 128;

    // ---- prologue ----
    if (tid == 0) {
        #pragma unroll
        for (int s = 0; s < STAGES; ++s) {
            MBAR_INIT(mbF + s * 8, 1);
            MBAR_INIT(mbE + s * 8, 16);
        }
        MBAR_INIT(mbx, 1);
    }
    __syncthreads();
    const unsigned char* gh = g_xh + (size_t)b * NT * IMG;
    if (tid == 0) {
        MBAR_EXPECT_TX(mbx, IMG);
        bulk_g2s(sb + XM_H, gh + (size_t)blockIdx.x * IMG, IMG, mbx);
        #pragma unroll
        for (int u = 0; u < 6; ++u) {
            MBAR_EXPECT_TX(mbF + u * 8, IMG);
            bulk_g2s(sb + XN_BASE + u * XN_STRIDE, gh + (size_t)u * IMG, IMG, mbF + u * 8);
        }
    }

    // per-warp address components
    const int mchunk = (wm >> 2) * 8192;
    const int mcol = (wm & 3) * 16 + l8;
    const int nchunk = wn * 8192;

    // per-thread K-column shifts (rows mA, mA+8)
    const int mA = wm * 16 + lq;
    const float ntsA = -g_tsh[(size_t)b * N + m0 + mA];
    const float ntsB = -g_tsh[(size_t)b * N + m0 + mA + 8];
    const float C = KBW * LOG2E;

    const uint32_t oneh = 0x3C003C00u;   // fp16 {1,1}
    const uint32_t bOne[2] = {oneh, oneh};

    float accO[8][4];
    #pragma unroll
    for (int j = 0; j < 8; ++j)
        #pragma unroll
        for (int c = 0; c < 4; ++c) accO[j][c] = 0.0f;
    float accD[4] = {0.0f, 0.0f, 0.0f, 0.0f};

    // ---- hoist Xmh A-fragments (loop-invariant, 16 regs) ----
    MBAR_WAIT(mbx, 0);
    uint32_t Ah[4][4];
    #pragma unroll
    for (int k = 0; k < 4; ++k) {
        const uint32_t offA =
            swz((uint32_t)((k * 16 + l7 + l16h) * 128 + mcol * 2)) + mchunk;
        LDSM_X4_T(Ah[k], sb + XM_H + offA);
    }

    for (int t = 0; t < NT; ++t) {
        // producer: prefetch tile t+6 into stage (t+6)%STAGES
        if (tid == 0) {
            const int u = t + 6;
            if (u < NT) {
                const int us = u & 7, uj = u >> 3;
                if (u >= STAGES) MBAR_WAIT(mbE + us * 8, (uj - 1) & 1);
                MBAR_EXPECT_TX(mbF + us * 8, IMG);
                bulk_g2s(sb + XN_BASE + us * XN_STRIDE, gh + (size_t)u * IMG,
                         IMG, mbF + us * 8);
            }
        }
        const int cs = t & 7;
        const uint32_t XNB = sb + XN_BASE + cs * XN_STRIDE;
        MBAR_WAIT(mbF + cs * 8, (t >> 3) & 1);

        // ---- MMA1: S[16m x 64n] = Xmh . Xnh, single fp16 pass, k = 64 ----
        float accS[8][4];
        #pragma unroll
        for (int j = 0; j < 8; ++j)
            #pragma unroll
            for (int c = 0; c < 4; ++c) accS[j][c] = 0.0f;

        #pragma unroll
        for (int k = 0; k < 4; ++k) {
            const int drowB = k * 16 + l7 + l8;
            #pragma unroll
            for (int np = 0; np < 4; ++np) {
                uint32_t Bh[4];
                const uint32_t offB =
                    swz((uint32_t)(drowB * 128 + (np * 16 + l16h) * 2)) + nchunk;
                LDSM_X4_T(Bh, XNB + offB);
                hmma(accS[2 * np],     Ah[k], Bh);
                hmma(accS[2 * np + 1], Ah[k], Bh + 2);
            }
        }

        // ---- per k-step: K' = 2^(C*S - tsh) via MUFU -> fp16 A -> MMA2 ----
        // O[16m x 64d] per warp += Kh . Xh, k = 64 n-slice; den via ones column
        #pragma unroll
        for (int ks = 0; ks < 4; ++ks) {
            uint32_t AK[4];
            #pragma unroll
            for (int h = 0; h < 2; ++h) {
                const float* s = accS[2 * ks + h];
                float e0 = ex2a(fmaf(s[0], C, ntsA));
                float e1 = ex2a(fmaf(s[1], C, ntsA));
                float e2 = ex2a(fmaf(s[2], C, ntsB));
                float e3 = ex2a(fmaf(s[3], C, ntsB));
                AK[2 * h]     = pack_f16(e1, e0);
                AK[2 * h + 1] = pack_f16(e3, e2);
            }
            hmma(accD, AK, bOne);
            const int kcol = ks * 16 + l8;
            #pragma unroll
            for (int dg = 0; dg < 4; ++dg) {
                const int dd = dg * 16 + l7 + l16h;
                const uint32_t off =
                    swz((uint32_t)(dd * 128 + kcol * 2)) + nchunk;
                uint32_t Bh[4];
                LDSM_X4(Bh, XNB + off);
                hmma(accO[2 * dg],     AK, Bh);
                hmma(accO[2 * dg + 1], AK, Bh + 2);
            }
        }

        // done reading stage cs
        if (l == 0) MBAR_ARRIVE(mbE + cs * 8);
    }

    // ---- den: accD[0]=rows lq, accD[2]=rows lq+8 (all quad lanes equal) ----
    float* sDen = (float*)(smc + SDEN);     // [2][128]
    if (lr == 0) {
        sDen[wn * 128 + mA] = accD[0];
        sDen[wn * 128 + mA + 8] = accD[2];
    }
    __syncthreads();   // all warps done with all tiles; sDen visible

    // ---- partial-O epilogue: scale by STEP/den, write per n-group region ----
    const int mB2 = mA + 8;
    const float scA = STEP / (sDen[mA] + sDen[128 + mA]);
    const float scB = STEP / (sDen[mB2] + sDen[128 + mB2]);
    float* sO = (float*)(smc + wn * 33792);   // [64 d][132 m]
    #pragma unroll
    for (int dg = 0; dg < 4; ++dg)
        #pragma unroll
        for (int s = 0; s < 2; ++s) {
            const float* c = accO[2 * dg + s];
            const int dbase = dg * 16 + s * 8 + 2 * lr;
            sO[dbase * 132 + mA]        = c[0] * scA;
            sO[(dbase + 1) * 132 + mA]  = c[1] * scA;
            sO[dbase * 132 + mB2]       = c[2] * scB;
            sO[(dbase + 1) * 132 + mB2] = c[3] * scB;
        }
    __syncthreads();

    // ---- combine partials + blend with x, store ----
    const float* sO0 = (const float*)(smc);
    const float* sO1 = (const float*)(smc + 33792);
    #pragma unroll
    for (int q = 0; q < 4; ++q) {
        int task = q * THREADS + tid;       // dd(64) x mq(32)
        int dd = task >> 5, mq = task & 31;
        float4 o0 = *(const float4*)&sO0[dd * 132 + mq * 4];
        float4 o1 = *(const float4*)&sO1[dd * 132 + mq * 4];
        float4 x = *(const float4*)(xin + (size_t)dd * N + m0 + mq * 4);
        float4 r;
        r.x = fmaf(1.0f - STEP, x.x, o0.x + o1.x);
        r.y = fmaf(1.0f - STEP, x.y, o0.y + o1.y);
        r.z = fmaf(1.0f - STEP, x.z, o0.z + o1.z);
        r.w = fmaf(1.0f - STEP, x.w, o0.w + o1.w);
        *(float4*)(xout + (size_t)dd * N + m0 + mq * 4) = r;
    }
}

extern "C" void kernel_launch(void* const* d_in, const int* in_sizes, int n_in,
                              void* d_out, int out_size) {
    const float* x = (const float*)d_in[0];
    float* out = (float*)d_out;

    cudaFuncSetAttribute(ms_mma_kernel,
                         cudaFuncAttributeMaxDynamicSharedMemorySize, SMEM_BYTES);

    int copy_total = B * D * N / 4;
    copy_x0_kernel<<<(copy_total + 255) / 256, 256>>>(x, out);

    dim3 grid(NT, B);
    for (int it = 0; it < ITERS; ++it) {
        convert_kernel<<<grid, 256>>>(out, it);
        ms_mma_kernel<<<grid, THREADS, SMEM_BYTES>>>(out, it);
    }
}

// round 12
// speedup vs baseline: 2.7483x; 1.0165x over previous
#include <cuda_runtime.h>
#include <cuda_fp16.h>
#include <cstdint>

// ---------------- problem constants ----------------
constexpr int B = 2;
constexpr int D = 64;
constexpr int N = 96 * 96;      // 9216
constexpr int ITERS = 4;
constexpr float STEP = 0.5f;
constexpr float KBW = 0.3f;
constexpr float LOG2E = 1.4426950408889634f;

constexpr int BM = 128;
constexpr int BN = 128;
constexpr int THREADS = 512;
constexpr int NT = N / BN;      // 72
constexpr int STAGES = 8;

// Tile image: 2 chunks x [64 d][64 pt] fp16, 128B swizzled rows = 16384 B
constexpr int IMG = 16384;

// ping-pong operand buffers (iter parity)
__device__ __align__(16) unsigned char g_xh[2][(size_t)B * NT * IMG];
__device__ float g_tsh[2][(size_t)B * N];

// ---------------- smem layout (bytes) ----------------
constexpr int XM_H = 0;              // 16 KB
constexpr int XN_BASE = 16384;       // STAGES x 16 KB
constexpr int XN_STRIDE = 16384;
constexpr int SDEN = XN_BASE + STAGES * XN_STRIDE;   // 147456; 256 f32
constexpr int MBAR = SDEN + 1024;
constexpr int SMEM_BYTES = MBAR + 256;
// epilogue reuse: sO0 f32[64][132] at 0, sO1 at 33792; then sP f32[16][128] at 0

// ---------------- asm helpers ----------------
__device__ __forceinline__ uint32_t smem_u32(const void* p) {
    uint32_t a;
    asm("{ .reg .u64 t; cvta.to.shared.u64 t, %1; cvt.u32.u64 %0, t; }"
        : "=r"(a) : "l"(p));
    return a;
}

__device__ __forceinline__ uint32_t swz(uint32_t o) {
    return o ^ ((o >> 3) & 0x70);
}

#define MBAR_INIT(mbar, cnt) \
    asm volatile("mbarrier.init.shared.b64 [%0], %1;" :: "r"(mbar), "r"(cnt) : "memory")

#define MBAR_EXPECT_TX(mbar, bytes) \
    asm volatile("mbarrier.arrive.expect_tx.shared.b64 _, [%0], %1;" \
                 :: "r"(mbar), "r"(bytes) : "memory")

#define MBAR_ARRIVE(mbar) \
    asm volatile("mbarrier.arrive.shared.b64 _, [%0];" :: "r"(mbar) : "memory")

#define MBAR_WAIT(mbar, parity) do {                                          \
    uint32_t _m = (mbar), _p = (parity);                                      \
    asm volatile(                                                             \
        "{\n\t.reg .pred P1;\n\t"                                             \
        "WAIT_LOOP_%=:\n\t"                                                   \
        "mbarrier.try_wait.parity.acquire.cta.shared::cta.b64 P1, [%0], %1, 0x989680;\n\t" \
        "@P1 bra.uni WAIT_DONE_%=;\n\t"                                       \
        "bra.uni WAIT_LOOP_%=;\n\t"                                           \
        "WAIT_DONE_%=:\n\t}"                                                  \
        :: "r"(_m), "r"(_p) : "memory");                                      \
} while (0)

__device__ __forceinline__ void bulk_g2s(uint32_t dst, const void* src,
                                         uint32_t bytes, uint32_t mbar) {
    asm volatile(
        "cp.async.bulk.shared::cluster.global.mbarrier::complete_tx::bytes "
        "[%0], [%1], %2, [%3];"
        :: "r"(dst), "l"(__cvta_generic_to_global(src)), "r"(bytes), "r"(mbar)
        : "memory");
}

#define LDSM_X4(r, addr)                                                     \
    asm volatile("ldmatrix.sync.aligned.m8n8.x4.shared.b16 {%0,%1,%2,%3}, [%4];" \
        : "=r"((r)[0]), "=r"((r)[1]), "=r"((r)[2]), "=r"((r)[3]) : "r"(addr))

#define LDSM_X4_T(r, addr)                                                   \
    asm volatile("ldmatrix.sync.aligned.m8n8.x4.trans.shared.b16 {%0,%1,%2,%3}, [%4];" \
        : "=r"((r)[0]), "=r"((r)[1]), "=r"((r)[2]), "=r"((r)[3]) : "r"(addr))

__device__ __forceinline__ void hmma(float* c, const uint32_t* a, const uint32_t* b) {
    asm volatile(
        "mma.sync.aligned.m16n8k16.row.col.f32.f16.f16.f32 "
        "{%0,%1,%2,%3}, {%4,%5,%6,%7}, {%8,%9}, {%0,%1,%2,%3};"
        : "+f"(c[0]), "+f"(c[1]), "+f"(c[2]), "+f"(c[3])
        : "r"(a[0]), "r"(a[1]), "r"(a[2]), "r"(a[3]), "r"(b[0]), "r"(b[1]));
}

// pack two f32 into f16x2 (lo = second arg), saturating to finite
__device__ __forceinline__ uint32_t pack_f16(float hi, float lo) {
    uint32_t r;
    asm("cvt.rn.satfinite.f16x2.f32 %0, %1, %2;" : "=r"(r) : "f"(hi), "f"(lo));
    return r;
}

// 2^t via MUFU (otherwise-idle pipe; ~2 ulp)
__device__ __forceinline__ float ex2a(float t) {
    float r;
    asm("ex2.approx.f32 %0, %1;" : "=f"(r) : "f"(t));
    return r;
}

// init: copy x0 into out slice 0, build fp16 image buf0 + tsh buf0
__global__ __launch_bounds__(256)
void init_kernel(const float* __restrict__ x, float* __restrict__ out) {
    const int t = blockIdx.x, b = blockIdx.y;
    const int tid = threadIdx.x;
    const float* xs = x + (size_t)b * D * N;
    float* os = out + (size_t)b * (ITERS + 1) * D * N;
    unsigned char* ph = g_xh[0] + (size_t)(b * NT + t) * IMG;
    #pragma unroll
    for (int q = 0; q < 4; ++q) {
        int task = q * 256 + tid;          // c(2) x d(64) x g(8)
        int c = task >> 9, rem = task & 511;
        int d = rem >> 3, g = rem & 7;
        int n0 = t * BN + c * 64 + g * 8;
        const float4* s = (const float4*)(xs + (size_t)d * N + n0);
        float4 v0 = s[0], v1 = s[1];
        float4* o = (float4*)(os + (size_t)d * N + n0);
        o[0] = v0;
        o[1] = v1;
        uint32_t hp[4];
        hp[0] = pack_f16(v0.y, v0.x);
        hp[1] = pack_f16(v0.w, v0.z);
        hp[2] = pack_f16(v1.y, v1.x);
        hp[3] = pack_f16(v1.w, v1.z);
        uint32_t off = c * 8192 + swz((uint32_t)(d * 128 + g * 16));
        *(uint4*)(ph + off) = make_uint4(hp[0], hp[1], hp[2], hp[3]);
    }
    if (tid < BN) {
        int n = t * BN + tid;
        float s = 0.0f;
        #pragma unroll 8
        for (int d = 0; d < D; ++d) {
            float v = xs[(size_t)d * N + n];
            s = fmaf(v, v, s);
        }
        g_tsh[0][(size_t)b * N + n] = fmaf(KBW * LOG2E, s, 2.0f);
    }
}

// ---------------- main kernel ----------------
__global__ __launch_bounds__(THREADS, 1)
void ms_mma_kernel(float* __restrict__ out, int it) {
    extern __shared__ unsigned char smc[];
    uint32_t sb = smem_u32(smc);

    const int tid = threadIdx.x;
    const int l = tid & 31;
    const int w = tid >> 5;
    const int wm = w >> 1;       // 8 m-groups of 16 rows
    const int wn = w & 1;        // 2 n-groups of 64 cols

    const int b = blockIdx.y;
    const int m0 = blockIdx.x * BM;
    const float* __restrict__ xin = out + ((size_t)b * (ITERS + 1) + it) * (size_t)(D * N);
    float* __restrict__ xout = (float*)xin + (size_t)D * N;

    const int l7 = l & 7, l8 = l & 8, l16h = (l & 16) >> 1, lq = l >> 2, lr = l & 3;

    const uint32_t mbF = sb + MBAR;            // full[8]
    const uint32_t mbE = sb + MBAR + 64;       // empty[8]
    const uint32_t mbx = sb + MBAR + 128;

    // ---- prologue ----
    if (tid == 0) {
        #pragma unroll
        for (int s = 0; s < STAGES; ++s) {
            MBAR_INIT(mbF + s * 8, 1);
            MBAR_INIT(mbE + s * 8, 16);
        }
        MBAR_INIT(mbx, 1);
    }
    __syncthreads();
    const unsigned char* gh = g_xh[it & 1] + (size_t)b * NT * IMG;
    if (tid == 0) {
        MBAR_EXPECT_TX(mbx, IMG);
        bulk_g2s(sb + XM_H, gh + (size_t)blockIdx.x * IMG, IMG, mbx);
        #pragma unroll
        for (int u = 0; u < 6; ++u) {
            MBAR_EXPECT_TX(mbF + u * 8, IMG);
            bulk_g2s(sb + XN_BASE + u * XN_STRIDE, gh + (size_t)u * IMG, IMG, mbF + u * 8);
        }
    }

    // per-warp address components
    const int mchunk = (wm >> 2) * 8192;
    const int mcol = (wm & 3) * 16 + l8;
    const int nchunk = wn * 8192;

    // per-thread K-column shifts (rows mA, mA+8)
    const int mA = wm * 16 + lq;
    const float ntsA = -g_tsh[it & 1][(size_t)b * N + m0 + mA];
    const float ntsB = -g_tsh[it & 1][(size_t)b * N + m0 + mA + 8];
    const float C = KBW * LOG2E;

    const uint32_t oneh = 0x3C003C00u;   // fp16 {1,1}
    const uint32_t bOne[2] = {oneh, oneh};

    float accO[8][4];
    #pragma unroll
    for (int j = 0; j < 8; ++j)
        #pragma unroll
        for (int c = 0; c < 4; ++c) accO[j][c] = 0.0f;
    float accD[4] = {0.0f, 0.0f, 0.0f, 0.0f};

    // ---- hoist Xmh A-fragments (loop-invariant, 16 regs) ----
    MBAR_WAIT(mbx, 0);
    uint32_t Ah[4][4];
    #pragma unroll
    for (int k = 0; k < 4; ++k) {
        const uint32_t offA =
            swz((uint32_t)((k * 16 + l7 + l16h) * 128 + mcol * 2)) + mchunk;
        LDSM_X4_T(Ah[k], sb + XM_H + offA);
    }

    for (int t = 0; t < NT; ++t) {
        // producer: prefetch tile t+6 into stage (t+6)%STAGES
        if (tid == 0) {
            const int u = t + 6;
            if (u < NT) {
                const int us = u & 7, uj = u >> 3;
                if (u >= STAGES) MBAR_WAIT(mbE + us * 8, (uj - 1) & 1);
                MBAR_EXPECT_TX(mbF + us * 8, IMG);
                bulk_g2s(sb + XN_BASE + us * XN_STRIDE, gh + (size_t)u * IMG,
                         IMG, mbF + us * 8);
            }
        }
        const int cs = t & 7;
        const uint32_t XNB = sb + XN_BASE + cs * XN_STRIDE;
        MBAR_WAIT(mbF + cs * 8, (t >> 3) & 1);

        // ---- fused per n-group: S-slice -> exp -> O-slice ----
        #pragma unroll
        for (int np = 0; np < 4; ++np) {
            float s0[4] = {0.0f, 0.0f, 0.0f, 0.0f};
            float s1[4] = {0.0f, 0.0f, 0.0f, 0.0f};
            #pragma unroll
            for (int k = 0; k < 4; ++k) {
                uint32_t Bh[4];
                const uint32_t offB =
                    swz((uint32_t)((k * 16 + l7 + l8) * 128 + (np * 16 + l16h) * 2))
                    + nchunk;
                LDSM_X4_T(Bh, XNB + offB);
                hmma(s0, Ah[k], Bh);
                hmma(s1, Ah[k], Bh + 2);
            }
            // K' = 2^(C*S - tsh) via MUFU -> fp16 A fragment
            uint32_t AK[4];
            AK[0] = pack_f16(ex2a(fmaf(s0[1], C, ntsA)), ex2a(fmaf(s0[0], C, ntsA)));
            AK[1] = pack_f16(ex2a(fmaf(s0[3], C, ntsB)), ex2a(fmaf(s0[2], C, ntsB)));
            AK[2] = pack_f16(ex2a(fmaf(s1[1], C, ntsA)), ex2a(fmaf(s1[0], C, ntsA)));
            AK[3] = pack_f16(ex2a(fmaf(s1[3], C, ntsB)), ex2a(fmaf(s1[2], C, ntsB)));
            hmma(accD, AK, bOne);
            const int kcol = np * 16 + l8;
            #pragma unroll
            for (int dg = 0; dg < 4; ++dg) {
                const int dd = dg * 16 + l7 + l16h;
                const uint32_t off =
                    swz((uint32_t)(dd * 128 + kcol * 2)) + nchunk;
                uint32_t B2[4];
                LDSM_X4(B2, XNB + off);
                hmma(accO[2 * dg],     AK, B2);
                hmma(accO[2 * dg + 1], AK, B2 + 2);
            }
        }

        // done reading stage cs
        if (l == 0) MBAR_ARRIVE(mbE + cs * 8);
    }

    // ---- den: accD[0]=rows lq, accD[2]=rows lq+8 (all quad lanes equal) ----
    float* sDen = (float*)(smc + SDEN);     // [2][128]
    if (lr == 0) {
        sDen[wn * 128 + mA] = accD[0];
        sDen[wn * 128 + mA + 8] = accD[2];
    }
    __syncthreads();   // all warps done with all tiles; sDen visible

    // ---- partial-O epilogue: scale by STEP/den, write per n-group region ----
    const int mB2 = mA + 8;
    const float scA = STEP / (sDen[mA] + sDen[128 + mA]);
    const float scB = STEP / (sDen[mB2] + sDen[128 + mB2]);
    float* sO = (float*)(smc + wn * 33792);   // [64 d][132 m]
    #pragma unroll
    for (int dg = 0; dg < 4; ++dg)
        #pragma unroll
        for (int s = 0; s < 2; ++s) {
            const float* c = accO[2 * dg + s];
            const int dbase = dg * 16 + s * 8 + 2 * lr;
            sO[dbase * 132 + mA]        = c[0] * scA;
            sO[(dbase + 1) * 132 + mA]  = c[1] * scA;
            sO[dbase * 132 + mB2]       = c[2] * scB;
            sO[(dbase + 1) * 132 + mB2] = c[3] * scB;
        }
    __syncthreads();

    // ---- combine partials + blend with x, store + next-iter image ----
    unsigned char* phn = g_xh[(it + 1) & 1] + (size_t)(b * NT + blockIdx.x) * IMG;
    const float* sO0 = (const float*)(smc);
    const float* sO1 = (const float*)(smc + 33792);
    float psum[4] = {0.0f, 0.0f, 0.0f, 0.0f};
    #pragma unroll
    for (int q = 0; q < 4; ++q) {
        int task = q * THREADS + tid;       // dd(64) x mq(32)
        int dd = task >> 5, mq = task & 31;
        float4 o0 = *(const float4*)&sO0[dd * 132 + mq * 4];
        float4 o1 = *(const float4*)&sO1[dd * 132 + mq * 4];
        float4 x = *(const float4*)(xin + (size_t)dd * N + m0 + mq * 4);
        float4 r;
        r.x = fmaf(1.0f - STEP, x.x, o0.x + o1.x);
        r.y = fmaf(1.0f - STEP, x.y, o0.y + o1.y);
        r.z = fmaf(1.0f - STEP, x.z, o0.z + o1.z);
        r.w = fmaf(1.0f - STEP, x.w, o0.w + o1.w);
        *(float4*)(xout + (size_t)dd * N + m0 + mq * 4) = r;
        // next-iteration fp16 image (ping-pong buffer)
        uint32_t hp0 = pack_f16(r.y, r.x);
        uint32_t hp1 = pack_f16(r.w, r.z);
        int mit = mq * 4;
        uint32_t off = (mit >> 6) * 8192
                     + swz((uint32_t)(dd * 128 + ((mit & 63) >> 3) * 16))
                     + (mit & 7) * 2;
        *(uint2*)(phn + off) = make_uint2(hp0, hp1);
        psum[0] = fmaf(r.x, r.x, psum[0]);
        psum[1] = fmaf(r.y, r.y, psum[1]);
        psum[2] = fmaf(r.z, r.z, psum[2]);
        psum[3] = fmaf(r.w, r.w, psum[3]);
    }
    __syncthreads();   // sO reads done; reuse region for norm reduction
    float* sP = (float*)smc;               // [16][128]
    {
        int grp = tid >> 5, mq = tid & 31;
        #pragma unroll
        for (int j = 0; j < 4; ++j)
            sP[grp * 128 + mq * 4 + j] = psum[j];
    }
    __syncthreads();
    if (tid < BM) {
        float s = 0.0f;
        #pragma unroll
        for (int g = 0; g < 16; ++g) s += sP[g * 128 + tid];
        g_tsh[(it + 1) & 1][(size_t)b * N + m0 + tid] = fmaf(C, s, 2.0f);
    }
}

extern "C" void kernel_launch(void* const* d_in, const int* in_sizes, int n_in,
                              void* d_out, int out_size) {
    const float* x = (const float*)d_in[0];
    float* out = (float*)d_out;

    cudaFuncSetAttribute(ms_mma_kernel,
                         cudaFuncAttributeMaxDynamicSharedMemorySize, SMEM_BYTES);

    dim3 grid(NT, B);
    init_kernel<<<grid, 256>>>(x, out);
    for (int it = 0; it < ITERS; ++it)
        ms_mma_kernel<<<grid, THREADS, SMEM_BYTES>>>(out, it);
}